// round 1
// baseline (speedup 1.0000x reference)
#include <cuda_runtime.h>
#include <cstdint>

// Problem constants
#define PP 64     // particles
#define HH 256    // hidden
#define EE 64     // input size
#define BB 32     // batch
#define SS 128    // seq len
#define G4 1024   // 4*H
#define NL 2048   // PP*BB lanes

#define ALPHA_F 0.1f
#define CMIX_F  0.0140625f         // (1-alpha)/P
#define TINY_F  1.17549435e-38f    // float32 tiny (smallest normal)

// ---------------- device scratch (no allocations allowed) ----------------
__device__ float g_xg[SS * BB * G4];   // x@W_ih^T + b_ih + b_hh, per (t,b)
__device__ float g_xdot[SS * BB];      // x . W_obs[:E]
__device__ float g_gates[NL * G4];     // h@W_hh^T per step
__device__ float g_h[2][NL * HH];
__device__ float g_c[2][NL * HH];
__device__ float g_htmp[NL * HH];      // pre-resample h1
__device__ float g_ctmp[NL * HH];      // pre-resample c1
__device__ float g_p[2][NL];           // log weights
__device__ uint2 g_sub[SS];            // per-step subkeys

// ---------------- threefry2x32 (JAX-compatible) ----------------
__device__ __forceinline__ void tf2x32(uint32_t k0, uint32_t k1,
                                       uint32_t x0, uint32_t x1,
                                       uint32_t& o0, uint32_t& o1) {
  uint32_t ks2 = k0 ^ k1 ^ 0x1BD11BDAu;
  x0 += k0; x1 += k1;
#define TFR(r) { x0 += x1; x1 = (x1 << (r)) | (x1 >> (32 - (r))); x1 ^= x0; }
  TFR(13) TFR(15) TFR(26) TFR(6)   x0 += k1;  x1 += ks2 + 1u;
  TFR(17) TFR(29) TFR(16) TFR(24)  x0 += ks2; x1 += k0  + 2u;
  TFR(13) TFR(15) TFR(26) TFR(6)   x0 += k0;  x1 += k1  + 3u;
  TFR(17) TFR(29) TFR(16) TFR(24)  x0 += k1;  x1 += ks2 + 4u;
  TFR(13) TFR(15) TFR(26) TFR(6)   x0 += ks2; x1 += k0  + 5u;
#undef TFR
  o0 = x0; o1 = x1;
}

// gumbel sample matching jax.random.gumbel with threefry_partitionable
// counter pair = (hi=0, lo=flat); 32-bit draw = out0 ^ out1
__device__ __forceinline__ float gumbel_from(uint32_t k0, uint32_t k1, uint32_t flat) {
  uint32_t o0, o1;
  tf2x32(k0, k1, 0u, flat, o0, o1);
  uint32_t bits = o0 ^ o1;
  float f = __uint_as_float((bits >> 9) | 0x3F800000u) - 1.0f;  // [0,1)
  f = fmaxf(f, TINY_F);                                        // uniform(minval=tiny)
  return -logf(-logf(f));
}

__device__ __forceinline__ float sigm(float x) { return 1.0f / (1.0f + expf(-x)); }
__device__ __forceinline__ float lrelu(float x) { return x >= 0.0f ? x : 0.01f * x; }

// ---------------- prologue kernels ----------------
// key chain: key0 = key(42) = (0,42); each step: key,sub = split(key)
// foldlike split: key_i = E_key(0, i); key = key_0, sub = key_1
__global__ void k_prep_keys() {
  if (threadIdx.x == 0 && blockIdx.x == 0) {
    uint32_t k0 = 0u, k1 = 42u;
    for (int t = 0; t < SS; t++) {
      uint32_t n0, n1, s0, s1;
      tf2x32(k0, k1, 0u, 0u, n0, n1);
      tf2x32(k0, k1, 0u, 1u, s0, s1);
      g_sub[t] = make_uint2(s0, s1);
      k0 = n0; k1 = n1;
    }
  }
}

__global__ void k_init(const float* __restrict__ h0, const float* __restrict__ c0) {
  int i = blockIdx.x * blockDim.x + threadIdx.x;
  if (i < NL * HH) { g_h[0][i] = h0[i]; g_c[0][i] = c0[i]; }
  if (i < NL) g_p[0][i] = (float)(-4.158883083359672);  // log(1/64)
}

// xg[t][b][n] = obs[b,t,:] . W_ih[n,:] + b_ih[n] + b_hh[n];  xdot = obs . W_obs[:E]
__global__ void k_xg(const float* __restrict__ obs, const float* __restrict__ Wih,
                     const float* __restrict__ bih, const float* __restrict__ bhh,
                     const float* __restrict__ Wobs) {
  int b = blockIdx.x, t = blockIdx.y;
  __shared__ float xs[EE];
  int tid = threadIdx.x;
  if (tid < EE) xs[tid] = obs[(b * SS + t) * EE + tid];
  __syncthreads();
  float* dst = g_xg + (t * BB + b) * G4;
  for (int n = tid; n < G4; n += 256) {
    const float* w = Wih + n * EE;
    float acc = 0.0f;
#pragma unroll
    for (int e = 0; e < EE; e++) acc = fmaf(w[e], xs[e], acc);
    dst[n] = acc + bih[n] + bhh[n];
  }
  if (tid == 0) {
    float acc = 0.0f;
    for (int e = 0; e < EE; e++) acc = fmaf(Wobs[e], xs[e], acc);
    g_xdot[t * BB + b] = acc;
  }
}

// ---------------- per-step GEMM: gates = h @ W_hh^T (2048x1024, K=256) ----------------
// 128x128 tile per CTA, 256 threads, 8x8 register tile each, fp32
__global__ void __launch_bounds__(256, 1) k_gemm(int cur, const float* __restrict__ Whh) {
  __shared__ float As[16][132];
  __shared__ float Bs[16][132];
  const float* __restrict__ A = g_h[cur];
  int bn = blockIdx.x;       // 0..7  (cols of gates)
  int bm = blockIdx.y;       // 0..15 (rows)
  int tid = threadIdx.x;
  int tx = tid & 15, ty = tid >> 4;
  int lr = tid >> 2;         // 0..63
  int lk = (tid & 3) << 2;   // 0,4,8,12
  const float* Ab = A + (bm * 128) * HH;
  const float* Bb = Whh + (bn * 128) * HH;
  float acc[8][8];
#pragma unroll
  for (int i = 0; i < 8; i++)
#pragma unroll
    for (int j = 0; j < 8; j++) acc[i][j] = 0.0f;

  for (int k0 = 0; k0 < HH; k0 += 16) {
    float4 a0 = *(const float4*)(Ab + lr * HH + k0 + lk);
    float4 a1 = *(const float4*)(Ab + (lr + 64) * HH + k0 + lk);
    float4 b0 = *(const float4*)(Bb + lr * HH + k0 + lk);
    float4 b1 = *(const float4*)(Bb + (lr + 64) * HH + k0 + lk);
    As[lk + 0][lr] = a0.x; As[lk + 1][lr] = a0.y; As[lk + 2][lr] = a0.z; As[lk + 3][lr] = a0.w;
    As[lk + 0][lr + 64] = a1.x; As[lk + 1][lr + 64] = a1.y; As[lk + 2][lr + 64] = a1.z; As[lk + 3][lr + 64] = a1.w;
    Bs[lk + 0][lr] = b0.x; Bs[lk + 1][lr] = b0.y; Bs[lk + 2][lr] = b0.z; Bs[lk + 3][lr] = b0.w;
    Bs[lk + 0][lr + 64] = b1.x; Bs[lk + 1][lr + 64] = b1.y; Bs[lk + 2][lr + 64] = b1.z; Bs[lk + 3][lr + 64] = b1.w;
    __syncthreads();
#pragma unroll
    for (int kk = 0; kk < 16; kk++) {
      float av[8], bv[8];
#pragma unroll
      for (int i = 0; i < 8; i++) av[i] = As[kk][ty * 8 + i];
#pragma unroll
      for (int j = 0; j < 8; j++) bv[j] = Bs[kk][tx * 8 + j];
#pragma unroll
      for (int i = 0; i < 8; i++)
#pragma unroll
        for (int j = 0; j < 8; j++) acc[i][j] = fmaf(av[i], bv[j], acc[i][j]);
    }
    __syncthreads();
  }
#pragma unroll
  for (int i = 0; i < 8; i++) {
    int row = bm * 128 + ty * 8 + i;
    float4 v0 = make_float4(acc[i][0], acc[i][1], acc[i][2], acc[i][3]);
    float4 v1 = make_float4(acc[i][4], acc[i][5], acc[i][6], acc[i][7]);
    *(float4*)(g_gates + row * G4 + bn * 128 + tx * 8) = v0;
    *(float4*)(g_gates + row * G4 + bn * 128 + tx * 8 + 4) = v1;
  }
}

// ---------------- per-step fused cell + softmax + resample + outputs ----------------
// one CTA per batch b (resampling is batch-local), 256 threads = 8 warps
__global__ void __launch_bounds__(256) k_cell(int t, int cur,
    const float* __restrict__ Wobs, const float* __restrict__ bobs,
    const float* __restrict__ Wout, const float* __restrict__ bout,
    float* __restrict__ out) {
  int b = blockIdx.x;
  int nxt = cur ^ 1;
  int tid = threadIdx.x;
  int w = tid >> 5, l = tid & 31;
  __shared__ float s_dobs[PP], s_dout[PP], s_p1[PP], s_logits[PP], s_pnew[PP];
  __shared__ int s_idx[PP];
  const float* __restrict__ xg = g_xg + (t * BB + b) * G4;
  const float* __restrict__ cold = g_c[cur];

  // phase 1: LSTM cell + per-particle dot reductions (warp w handles particles w, w+8, ...)
  for (int p = w; p < PP; p += 8) {
    int r = p * BB + b;
    const float* grow = g_gates + (size_t)r * G4;
    float aobs = 0.0f, aout = 0.0f;
#pragma unroll
    for (int u = 0; u < 8; u++) {
      int j = l + (u << 5);
      float ig = grow[j] + xg[j];
      float fg = grow[HH + j] + xg[HH + j];
      float gg = grow[2 * HH + j] + xg[2 * HH + j];
      float og = grow[3 * HH + j] + xg[3 * HH + j];
      float c1 = sigm(fg) * cold[r * HH + j] + sigm(ig) * tanhf(gg);
      float h1 = sigm(og) * tanhf(c1);
      g_ctmp[r * HH + j] = c1;
      g_htmp[r * HH + j] = h1;
      aobs = fmaf(Wobs[EE + j], h1, aobs);
      aout = fmaf(Wout[j], h1, aout);
    }
#pragma unroll
    for (int off = 16; off; off >>= 1) {
      aobs += __shfl_xor_sync(0xffffffffu, aobs, off);
      aout += __shfl_xor_sync(0xffffffffu, aout, off);
    }
    if (l == 0) { s_dobs[p] = aobs; s_dout[p] = aout; }
  }
  __syncthreads();

  // phase 2 (warp 0): p1 = log_softmax over particles; logits = log(alpha*exp(p1)+(1-a)/P)
  if (w == 0) {
    float xd = g_xdot[t * BB + b] + bobs[0];
    int pa = l, pb = l + 32;
    float v0 = s_dobs[pa] + xd + g_p[cur][pa * BB + b];
    float v1 = s_dobs[pb] + xd + g_p[cur][pb * BB + b];
    float m = fmaxf(v0, v1);
#pragma unroll
    for (int off = 16; off; off >>= 1) m = fmaxf(m, __shfl_xor_sync(0xffffffffu, m, off));
    float es = expf(v0 - m) + expf(v1 - m);
#pragma unroll
    for (int off = 16; off; off >>= 1) es += __shfl_xor_sync(0xffffffffu, es, off);
    float ls = logf(es);
    float q0 = v0 - m - ls, q1 = v1 - m - ls;
    s_p1[pa] = q0; s_p1[pb] = q1;
    // match jnp expression exactly: log(ALPHA*exp(q) + C) without FMA contraction
    s_logits[pa] = logf(__fadd_rn(__fmul_rn(ALPHA_F, expf(q0)), CMIX_F));
    s_logits[pb] = logf(__fadd_rn(__fmul_rn(ALPHA_F, expf(q1)), CMIX_F));
  }
  __syncthreads();

  // phase 3: categorical sampling via gumbel-argmax; warp w handles draws w, w+8, ...
  uint2 sub = g_sub[t];
  for (int i = w; i < PP; i += 8) {
    uint32_t base = (uint32_t)(i * NL + b * PP);  // flat = i*2048 + b*64 + p
    float g0 = gumbel_from(sub.x, sub.y, base + (uint32_t)l) + s_logits[l];
    float g1 = gumbel_from(sub.x, sub.y, base + (uint32_t)(l + 32)) + s_logits[l + 32];
    float best = g0; int bi = l;
    if (g1 > best) { best = g1; bi = l + 32; }   // tie -> lower index (argmax first-max)
#pragma unroll
    for (int off = 16; off; off >>= 1) {
      float ov = __shfl_xor_sync(0xffffffffu, best, off);
      int oi = __shfl_xor_sync(0xffffffffu, bi, off);
      if (ov > best || (ov == best && oi < bi)) { best = ov; bi = oi; }
    }
    if (l == 0) s_idx[i] = bi;
  }
  __syncthreads();

  // phase 4 (warp 0): reweight, log_softmax over draws, y output
  if (w == 0) {
    // log(w_new) == logits[idx] (identical float expression)
    float lw0 = s_logits[s_idx[l]];
    float lw1 = s_logits[s_idx[l + 32]];
    float m2 = fmaxf(lw0, lw1);
#pragma unroll
    for (int off = 16; off; off >>= 1) m2 = fmaxf(m2, __shfl_xor_sync(0xffffffffu, m2, off));
    float es = expf(lw0 - m2) + expf(lw1 - m2);
#pragma unroll
    for (int off = 16; off; off >>= 1) es += __shfl_xor_sync(0xffffffffu, es, off);
    float ls2 = logf(es);
    float pn0 = lw0 - m2 - ls2, pn1 = lw1 - m2 - ls2;
    s_pnew[l] = pn0; s_pnew[l + 32] = pn1;
    float yl = expf(pn0) * s_dout[s_idx[l]] + expf(pn1) * s_dout[s_idx[l + 32]];
#pragma unroll
    for (int off = 16; off; off >>= 1) yl += __shfl_xor_sync(0xffffffffu, yl, off);
    if (l == 0) out[t * BB + b] = lrelu(yl + bout[0]);
  }
  __syncthreads();

  // phase 5: pf_out, new log-weights, gather h/c
  if (tid < PP) {
    int i = tid;
    float d = s_dout[s_idx[i]] + bout[0];
    out[SS * BB + (size_t)t * NL + i * BB + b] = lrelu(d);
    g_p[nxt][i * BB + b] = s_pnew[i];
  }
  for (int e = tid; e < PP * HH; e += 256) {
    int i = e >> 8, j = e & 255;
    int rs = s_idx[i] * BB + b;
    int rd = i * BB + b;
    g_h[nxt][rd * HH + j] = g_htmp[rs * HH + j];
    g_c[nxt][rd * HH + j] = g_ctmp[rs * HH + j];
  }
}

// ---------------- launch ----------------
extern "C" void kernel_launch(void* const* d_in, const int* in_sizes, int n_in,
                              void* d_out, int out_size) {
  const float* obs  = (const float*)d_in[0];
  const float* h0   = (const float*)d_in[1];
  const float* c0   = (const float*)d_in[2];
  const float* Wih  = (const float*)d_in[3];
  const float* bih  = (const float*)d_in[4];
  const float* Whh  = (const float*)d_in[5];
  const float* bhh  = (const float*)d_in[6];
  const float* Wobs = (const float*)d_in[7];
  const float* bobs = (const float*)d_in[8];
  const float* Wout = (const float*)d_in[9];
  const float* bout = (const float*)d_in[10];
  float* out = (float*)d_out;

  k_prep_keys<<<1, 1>>>();
  k_init<<<(NL * HH + 255) / 256, 256>>>(h0, c0);
  k_xg<<<dim3(BB, SS), 256>>>(obs, Wih, bih, bhh, Wobs);

  for (int t = 0; t < SS; t++) {
    int cur = t & 1;
    k_gemm<<<dim3(8, 16), 256>>>(cur, Whh);
    k_cell<<<BB, 256>>>(t, cur, Wobs, bobs, Wout, bout, out);
  }
  (void)in_sizes; (void)n_in; (void)out_size;
}

// round 2
// speedup vs baseline: 2.0039x; 2.0039x over previous
#include <cuda_runtime.h>
#include <cstdint>

// Problem constants
#define PP 64     // particles
#define HH 256    // hidden
#define EE 64     // input size
#define BB 32     // batch
#define SS 128    // seq len
#define G4 1024   // 4*H
#define NL 2048   // PP*BB lanes

#define ALPHA_F 0.1f
#define CMIX_F  0.0140625f         // (1-alpha)/P
#define TINY_F  1.17549435e-38f    // float32 tiny (smallest normal)

// ---------------- device scratch (no allocations allowed) ----------------
__device__ float g_xg[SS * BB * G4];   // x@W_ih^T + b_ih + b_hh, PERMUTED gate layout (col 4u+g)
__device__ float g_xdot[SS * BB];      // x . W_obs[:E]
__device__ float g_Whh[G4 * HH];       // W_hh rows permuted: row 4u+g = orig row g*H+u
__device__ float g_hbuf[2][NL * HH];   // ping-pong pre-resample h state
__device__ float g_cbuf[2][NL * HH];   // ping-pong pre-resample c state
__device__ int   g_perm[NL];           // resampling permutation (row -> source row)
__device__ float g_p[NL];              // log weights
__device__ float g_pobs[8][NL];        // partial obs dots per N-block
__device__ float g_pout[8][NL];        // partial out dots per N-block
__device__ uint2 g_sub[SS];            // per-step subkeys

// ---------------- threefry2x32 (JAX-compatible) ----------------
__device__ __forceinline__ void tf2x32(uint32_t k0, uint32_t k1,
                                       uint32_t x0, uint32_t x1,
                                       uint32_t& o0, uint32_t& o1) {
  uint32_t ks2 = k0 ^ k1 ^ 0x1BD11BDAu;
  x0 += k0; x1 += k1;
#define TFR(r) { x0 += x1; x1 = (x1 << (r)) | (x1 >> (32 - (r))); x1 ^= x0; }
  TFR(13) TFR(15) TFR(26) TFR(6)   x0 += k1;  x1 += ks2 + 1u;
  TFR(17) TFR(29) TFR(16) TFR(24)  x0 += ks2; x1 += k0  + 2u;
  TFR(13) TFR(15) TFR(26) TFR(6)   x0 += k0;  x1 += k1  + 3u;
  TFR(17) TFR(29) TFR(16) TFR(24)  x0 += k1;  x1 += ks2 + 4u;
  TFR(13) TFR(15) TFR(26) TFR(6)   x0 += ks2; x1 += k0  + 5u;
#undef TFR
  o0 = x0; o1 = x1;
}

__device__ __forceinline__ float gumbel_from(uint32_t k0, uint32_t k1, uint32_t flat) {
  uint32_t o0, o1;
  tf2x32(k0, k1, 0u, flat, o0, o1);
  uint32_t bits = o0 ^ o1;
  float f = __uint_as_float((bits >> 9) | 0x3F800000u) - 1.0f;  // [0,1)
  f = fmaxf(f, TINY_F);
  return -logf(-logf(f));
}

__device__ __forceinline__ float sigm(float x) { return 1.0f / (1.0f + expf(-x)); }
__device__ __forceinline__ float lrelu(float x) { return x >= 0.0f ? x : 0.01f * x; }

// ---------------- prologue kernels ----------------
__global__ void k_prep_keys() {
  if (threadIdx.x == 0 && blockIdx.x == 0) {
    uint32_t k0 = 0u, k1 = 42u;
    for (int t = 0; t < SS; t++) {
      uint32_t n0, n1, s0, s1;
      tf2x32(k0, k1, 0u, 0u, n0, n1);
      tf2x32(k0, k1, 0u, 1u, s0, s1);
      g_sub[t] = make_uint2(s0, s1);
      k0 = n0; k1 = n1;
    }
  }
}

__global__ void k_init(const float* __restrict__ h0, const float* __restrict__ c0) {
  int i = blockIdx.x * blockDim.x + threadIdx.x;
  if (i < NL * HH) { g_hbuf[0][i] = h0[i]; g_cbuf[0][i] = c0[i]; }
  if (i < NL) { g_p[i] = (float)(-4.158883083359672); g_perm[i] = i; }
}

// permute W_hh rows: dst row n = 4u+g  <-  src row g*H+u
__global__ void k_permW(const float* __restrict__ Whh) {
  int n = blockIdx.x;
  int u = n >> 2, g = n & 3;
  g_Whh[n * HH + threadIdx.x] = Whh[(g * HH + u) * HH + threadIdx.x];
}

// xg[t][b][n'] (permuted) = obs . W_ih[row] + b_ih[row] + b_hh[row], row = g*H+u, n'=4u+g
__global__ void k_xg(const float* __restrict__ obs, const float* __restrict__ Wih,
                     const float* __restrict__ bih, const float* __restrict__ bhh,
                     const float* __restrict__ Wobs) {
  int b = blockIdx.x, t = blockIdx.y;
  __shared__ float xs[EE];
  int tid = threadIdx.x;
  if (tid < EE) xs[tid] = obs[(b * SS + t) * EE + tid];
  __syncthreads();
  float* dst = g_xg + (t * BB + b) * G4;
  for (int n = tid; n < G4; n += 256) {
    int u = n >> 2, g = n & 3;
    int src = g * HH + u;
    const float* w = Wih + src * EE;
    float acc = 0.0f;
#pragma unroll
    for (int e = 0; e < EE; e++) acc = fmaf(w[e], xs[e], acc);
    dst[n] = acc + bih[src] + bhh[src];
  }
  if (tid == 0) {
    float acc = 0.0f;
    for (int e = 0; e < EE; e++) acc = fmaf(Wobs[e], xs[e], acc);
    g_xdot[t * BB + b] = acc;
  }
}

// ---------------- fused GEMM + LSTM cell ----------------
// gates = hbuf[cur][perm] @ Whh_perm^T  (2048x1024, K=256), epilogue applies cell,
// writes hbuf/cbuf[nxt] and partial obs/out dots. 128x128 tile per CTA, 8x8 reg tiles.
__global__ void __launch_bounds__(256, 1) k_fused(int t,
    const float* __restrict__ Wobs, const float* __restrict__ Wout) {
  int cur = t & 1, nxt = cur ^ 1;
  __shared__ float As[16][132];
  __shared__ float Bs[16][132];
  __shared__ float s_xgb[BB][132];   // xg slice for this CTA's 128 cols, all 32 b
  __shared__ int   s_perm[128];
  __shared__ float s_wo[32], s_wu[32];

  int bn = blockIdx.x;       // 0..7  (col block)
  int bm = blockIdx.y;       // 0..15 (row block)
  int tid = threadIdx.x;
  int tx = tid & 15, ty = tid >> 4;
  int lr = tid >> 2;         // 0..63
  int lk = (tid & 3) << 2;   // 0,4,8,12

  if (tid < 128) s_perm[tid] = g_perm[bm * 128 + tid];
  if (tid < 32) {
    s_wo[tid] = Wobs[EE + bn * 32 + tid];
    s_wu[tid] = Wout[bn * 32 + tid];
  }
  // xg: 32 b x 128 cols
  {
    const float* src = g_xg + (size_t)(t * BB) * G4 + bn * 128;
    for (int e = tid; e < BB * 128; e += 256) {
      int b = e >> 7, col = e & 127;
      s_xgb[b][col] = src[(size_t)b * G4 + col];
    }
  }
  __syncthreads();

  const float* __restrict__ Acur = g_hbuf[cur];
  const float* Ar0 = Acur + (size_t)s_perm[lr] * HH + lk;
  const float* Ar1 = Acur + (size_t)s_perm[lr + 64] * HH + lk;
  const float* Br0 = g_Whh + (size_t)(bn * 128 + lr) * HH + lk;
  const float* Br1 = g_Whh + (size_t)(bn * 128 + lr + 64) * HH + lk;

  float acc[8][8];
#pragma unroll
  for (int i = 0; i < 8; i++)
#pragma unroll
    for (int j = 0; j < 8; j++) acc[i][j] = 0.0f;

  // prefetch chunk 0
  float4 pa0 = *(const float4*)(Ar0);
  float4 pa1 = *(const float4*)(Ar1);
  float4 pb0 = *(const float4*)(Br0);
  float4 pb1 = *(const float4*)(Br1);

  for (int k0 = 0; k0 < HH; k0 += 16) {
    As[lk + 0][lr] = pa0.x; As[lk + 1][lr] = pa0.y; As[lk + 2][lr] = pa0.z; As[lk + 3][lr] = pa0.w;
    As[lk + 0][lr + 64] = pa1.x; As[lk + 1][lr + 64] = pa1.y; As[lk + 2][lr + 64] = pa1.z; As[lk + 3][lr + 64] = pa1.w;
    Bs[lk + 0][lr] = pb0.x; Bs[lk + 1][lr] = pb0.y; Bs[lk + 2][lr] = pb0.z; Bs[lk + 3][lr] = pb0.w;
    Bs[lk + 0][lr + 64] = pb1.x; Bs[lk + 1][lr + 64] = pb1.y; Bs[lk + 2][lr + 64] = pb1.z; Bs[lk + 3][lr + 64] = pb1.w;
    __syncthreads();
    if (k0 + 16 < HH) {
      pa0 = *(const float4*)(Ar0 + k0 + 16);
      pa1 = *(const float4*)(Ar1 + k0 + 16);
      pb0 = *(const float4*)(Br0 + k0 + 16);
      pb1 = *(const float4*)(Br1 + k0 + 16);
    }
#pragma unroll
    for (int kk = 0; kk < 16; kk++) {
      float4 av0 = *(const float4*)&As[kk][ty * 8];
      float4 av1 = *(const float4*)&As[kk][ty * 8 + 4];
      float4 bv0 = *(const float4*)&Bs[kk][tx * 8];
      float4 bv1 = *(const float4*)&Bs[kk][tx * 8 + 4];
      float av[8] = {av0.x, av0.y, av0.z, av0.w, av1.x, av1.y, av1.z, av1.w};
      float bv[8] = {bv0.x, bv0.y, bv0.z, bv0.w, bv1.x, bv1.y, bv1.z, bv1.w};
#pragma unroll
      for (int i = 0; i < 8; i++)
#pragma unroll
        for (int j = 0; j < 8; j++) acc[i][j] = fmaf(av[i], bv[j], acc[i][j]);
    }
    __syncthreads();
  }

  // ---------------- epilogue: LSTM cell + partial dots ----------------
  // thread covers rows ty*8..+7, units u0 = bn*32+tx*2 and u0+1
  int ul0 = tx * 2;                 // local unit within CTA's 32
  int u0 = bn * 32 + ul0;
  float* __restrict__ Hn = g_hbuf[nxt];
  float* __restrict__ Cn = g_cbuf[nxt];
  const float* __restrict__ Cc = g_cbuf[cur];
  float w_o0 = s_wo[ul0], w_o1 = s_wo[ul0 + 1];
  float w_u0 = s_wu[ul0], w_u1 = s_wu[ul0 + 1];

  float obsr[8], outr[8];
#pragma unroll
  for (int i = 0; i < 8; i++) {
    int lrow = ty * 8 + i;
    int row = bm * 128 + lrow;
    int b = lrow & 31;
    int src = s_perm[lrow];
    float4 xv0 = *(const float4*)&s_xgb[b][tx * 8];
    float4 xv1 = *(const float4*)&s_xgb[b][tx * 8 + 4];
    float2 cold = *(const float2*)(Cc + (size_t)src * HH + u0);
    // unit 0: gates i,f,g,o in acc[i][0..3]
    float ig0 = acc[i][0] + xv0.x;
    float fg0 = acc[i][1] + xv0.y;
    float gg0 = acc[i][2] + xv0.z;
    float og0 = acc[i][3] + xv0.w;
    float c10 = sigm(fg0) * cold.x + sigm(ig0) * tanhf(gg0);
    float h10 = sigm(og0) * tanhf(c10);
    // unit 1
    float ig1 = acc[i][4] + xv1.x;
    float fg1 = acc[i][5] + xv1.y;
    float gg1 = acc[i][6] + xv1.z;
    float og1 = acc[i][7] + xv1.w;
    float c11 = sigm(fg1) * cold.y + sigm(ig1) * tanhf(gg1);
    float h11 = sigm(og1) * tanhf(c11);
    *(float2*)(Hn + (size_t)row * HH + u0) = make_float2(h10, h11);
    *(float2*)(Cn + (size_t)row * HH + u0) = make_float2(c10, c11);
    obsr[i] = w_o0 * h10 + w_o1 * h11;
    outr[i] = w_u0 * h10 + w_u1 * h11;
  }
  // reduce across tx (16 lanes within half-warp)
#pragma unroll
  for (int off = 8; off; off >>= 1) {
#pragma unroll
    for (int i = 0; i < 8; i++) {
      obsr[i] += __shfl_xor_sync(0xffffffffu, obsr[i], off);
      outr[i] += __shfl_xor_sync(0xffffffffu, outr[i], off);
    }
  }
  if (tx == 0) {
#pragma unroll
    for (int i = 0; i < 8; i++) {
      int row = bm * 128 + ty * 8 + i;
      g_pobs[bn][row] = obsr[i];
      g_pout[bn][row] = outr[i];
    }
  }
}

// ---------------- per-step resample + outputs ----------------
// one CTA per batch b, 256 threads = 8 warps
__global__ void __launch_bounds__(256) k_resample(int t,
    const float* __restrict__ bobs, const float* __restrict__ bout,
    float* __restrict__ out) {
  int b = blockIdx.x;
  int tid = threadIdx.x;
  int w = tid >> 5, l = tid & 31;
  __shared__ float s_dobs[PP], s_dout[PP], s_logits[PP], s_pnew[PP];
  __shared__ int s_idx[PP];

  // sum partials over 8 N-blocks
  if (tid < PP) {
    int r = tid * BB + b;
    float so = 0.0f, du = 0.0f;
#pragma unroll
    for (int bn = 0; bn < 8; bn++) { so += g_pobs[bn][r]; du += g_pout[bn][r]; }
    s_dobs[tid] = so; s_dout[tid] = du;
  }
  __syncthreads();

  // warp 0: p1 = log_softmax over particles; logits = log(alpha*exp(p1)+(1-a)/P)
  if (w == 0) {
    float xd = g_xdot[t * BB + b] + bobs[0];
    int pa = l, pb = l + 32;
    float v0 = s_dobs[pa] + xd + g_p[pa * BB + b];
    float v1 = s_dobs[pb] + xd + g_p[pb * BB + b];
    float m = fmaxf(v0, v1);
#pragma unroll
    for (int off = 16; off; off >>= 1) m = fmaxf(m, __shfl_xor_sync(0xffffffffu, m, off));
    float es = expf(v0 - m) + expf(v1 - m);
#pragma unroll
    for (int off = 16; off; off >>= 1) es += __shfl_xor_sync(0xffffffffu, es, off);
    float ls = logf(es);
    float q0 = v0 - m - ls, q1 = v1 - m - ls;
    s_logits[pa] = logf(__fadd_rn(__fmul_rn(ALPHA_F, expf(q0)), CMIX_F));
    s_logits[pb] = logf(__fadd_rn(__fmul_rn(ALPHA_F, expf(q1)), CMIX_F));
  }
  __syncthreads();

  // categorical sampling via gumbel-argmax; warp w handles draws w, w+8, ...
  uint2 sub = g_sub[t];
  for (int i = w; i < PP; i += 8) {
    uint32_t base = (uint32_t)(i * NL + b * PP);
    float g0 = gumbel_from(sub.x, sub.y, base + (uint32_t)l) + s_logits[l];
    float g1 = gumbel_from(sub.x, sub.y, base + (uint32_t)(l + 32)) + s_logits[l + 32];
    float best = g0; int bi = l;
    if (g1 > best) { best = g1; bi = l + 32; }
#pragma unroll
    for (int off = 16; off; off >>= 1) {
      float ov = __shfl_xor_sync(0xffffffffu, best, off);
      int oi = __shfl_xor_sync(0xffffffffu, bi, off);
      if (ov > best || (ov == best && oi < bi)) { best = ov; bi = oi; }
    }
    if (l == 0) s_idx[i] = bi;
  }
  __syncthreads();

  // warp 0: reweight, log_softmax over draws, y output
  if (w == 0) {
    float lw0 = s_logits[s_idx[l]];
    float lw1 = s_logits[s_idx[l + 32]];
    float m2 = fmaxf(lw0, lw1);
#pragma unroll
    for (int off = 16; off; off >>= 1) m2 = fmaxf(m2, __shfl_xor_sync(0xffffffffu, m2, off));
    float es = expf(lw0 - m2) + expf(lw1 - m2);
#pragma unroll
    for (int off = 16; off; off >>= 1) es += __shfl_xor_sync(0xffffffffu, es, off);
    float ls2 = logf(es);
    float pn0 = lw0 - m2 - ls2, pn1 = lw1 - m2 - ls2;
    s_pnew[l] = pn0; s_pnew[l + 32] = pn1;
    float yl = expf(pn0) * s_dout[s_idx[l]] + expf(pn1) * s_dout[s_idx[l + 32]];
#pragma unroll
    for (int off = 16; off; off >>= 1) yl += __shfl_xor_sync(0xffffffffu, yl, off);
    if (l == 0) out[t * BB + b] = lrelu(yl + bout[0]);
  }
  __syncthreads();

  // pf_out, new log-weights, next-step permutation
  if (tid < PP) {
    int i = tid;
    float d = s_dout[s_idx[i]] + bout[0];
    out[SS * BB + (size_t)t * NL + i * BB + b] = lrelu(d);
    g_p[i * BB + b] = s_pnew[i];
    g_perm[i * BB + b] = s_idx[i] * BB + b;
  }
}

// ---------------- launch ----------------
extern "C" void kernel_launch(void* const* d_in, const int* in_sizes, int n_in,
                              void* d_out, int out_size) {
  const float* obs  = (const float*)d_in[0];
  const float* h0   = (const float*)d_in[1];
  const float* c0   = (const float*)d_in[2];
  const float* Wih  = (const float*)d_in[3];
  const float* bih  = (const float*)d_in[4];
  const float* Whh  = (const float*)d_in[5];
  const float* bhh  = (const float*)d_in[6];
  const float* Wobs = (const float*)d_in[7];
  const float* bobs = (const float*)d_in[8];
  const float* Wout = (const float*)d_in[9];
  const float* bout = (const float*)d_in[10];
  float* out = (float*)d_out;

  k_prep_keys<<<1, 1>>>();
  k_init<<<(NL * HH + 255) / 256, 256>>>(h0, c0);
  k_permW<<<G4, HH>>>(Whh);
  k_xg<<<dim3(BB, SS), 256>>>(obs, Wih, bih, bhh, Wobs);

  for (int t = 0; t < SS; t++) {
    k_fused<<<dim3(8, 16), 256>>>(t, Wobs, Wout);
    k_resample<<<BB, 256>>>(t, bobs, bout, out);
  }
  (void)in_sizes; (void)n_in; (void)out_size;
}

// round 3
// speedup vs baseline: 2.2787x; 1.1372x over previous
#include <cuda_runtime.h>
#include <cstdint>

// Problem constants
#define PP 64     // particles
#define HH 256    // hidden
#define EE 64     // input size
#define BB 32     // batch
#define SS 128    // seq len
#define G4 1024   // 4*H
#define NL 2048   // PP*BB lanes

#define ALPHA_F 0.1f
#define CMIX_F  0.0140625f         // (1-alpha)/P
#define TINY_F  1.17549435e-38f    // float32 tiny (smallest normal)

// ---------------- device scratch (no allocations allowed) ----------------
__device__ float g_xg[SS * BB * G4];   // x@W_ih^T + biases, PERMUTED gate layout (col 4u+g)
__device__ float g_xdot[SS * BB];      // x . W_obs[:E]
__device__ float g_Whh[G4 * HH];       // W_hh rows permuted: row 4u+g = orig row g*H+u
__device__ float g_Wih[G4 * EE];       // W_ih rows permuted likewise
__device__ float g_bias[G4];           // b_ih + b_hh, permuted
__device__ float g_hbuf[2][NL * HH];   // ping-pong pre-resample h state
__device__ float g_cbuf[2][NL * HH];   // ping-pong pre-resample c state
__device__ int   g_perm[NL];           // resampling permutation (row -> source row)
__device__ float g_p[NL];              // log weights
__device__ float g_pobs[8][NL];        // partial obs dots per N-block
__device__ float g_pout[8][NL];        // partial out dots per N-block
__device__ uint2 g_sub[SS];            // per-step subkeys

// ---------------- packed f32x2 helpers ----------------
__device__ __forceinline__ void ffma2(unsigned long long& d, unsigned long long a,
                                      unsigned long long b) {
  asm("fma.rn.f32x2 %0, %1, %2, %0;" : "+l"(d) : "l"(a), "l"(b));
}
__device__ __forceinline__ unsigned long long dup2(float a) {
  unsigned long long r;
  asm("mov.b64 %0, {%1, %1};" : "=l"(r) : "f"(a));
  return r;
}
__device__ __forceinline__ void unpk2(unsigned long long v, float& lo, float& hi) {
  asm("mov.b64 {%0, %1}, %2;" : "=f"(lo), "=f"(hi) : "l"(v));
}

// ---------------- threefry2x32 (JAX-compatible) ----------------
__device__ __forceinline__ void tf2x32(uint32_t k0, uint32_t k1,
                                       uint32_t x0, uint32_t x1,
                                       uint32_t& o0, uint32_t& o1) {
  uint32_t ks2 = k0 ^ k1 ^ 0x1BD11BDAu;
  x0 += k0; x1 += k1;
#define TFR(r) { x0 += x1; x1 = (x1 << (r)) | (x1 >> (32 - (r))); x1 ^= x0; }
  TFR(13) TFR(15) TFR(26) TFR(6)   x0 += k1;  x1 += ks2 + 1u;
  TFR(17) TFR(29) TFR(16) TFR(24)  x0 += ks2; x1 += k0  + 2u;
  TFR(13) TFR(15) TFR(26) TFR(6)   x0 += k0;  x1 += k1  + 3u;
  TFR(17) TFR(29) TFR(16) TFR(24)  x0 += k1;  x1 += ks2 + 4u;
  TFR(13) TFR(15) TFR(26) TFR(6)   x0 += ks2; x1 += k0  + 5u;
#undef TFR
  o0 = x0; o1 = x1;
}

__device__ __forceinline__ float gumbel_from(uint32_t k0, uint32_t k1, uint32_t flat) {
  uint32_t o0, o1;
  tf2x32(k0, k1, 0u, flat, o0, o1);
  uint32_t bits = o0 ^ o1;
  float f = __uint_as_float((bits >> 9) | 0x3F800000u) - 1.0f;  // [0,1)
  f = fmaxf(f, TINY_F);
  return -logf(-logf(f));
}

__device__ __forceinline__ float sigm(float x) { return 1.0f / (1.0f + expf(-x)); }
__device__ __forceinline__ float lrelu(float x) { return x >= 0.0f ? x : 0.01f * x; }

// ---------------- prologue kernels ----------------
__global__ void k_prep_keys() {
  if (threadIdx.x == 0 && blockIdx.x == 0) {
    uint32_t k0 = 0u, k1 = 42u;
    for (int t = 0; t < SS; t++) {
      uint32_t n0, n1, s0, s1;
      tf2x32(k0, k1, 0u, 0u, n0, n1);
      tf2x32(k0, k1, 0u, 1u, s0, s1);
      g_sub[t] = make_uint2(s0, s1);
      k0 = n0; k1 = n1;
    }
  }
}

__global__ void k_init(const float* __restrict__ h0, const float* __restrict__ c0) {
  int i = blockIdx.x * blockDim.x + threadIdx.x;
  if (i < NL * HH) { g_hbuf[0][i] = h0[i]; g_cbuf[0][i] = c0[i]; }
  if (i < NL) { g_p[i] = (float)(-4.158883083359672); g_perm[i] = i; }
}

// permute rows: dst row n = 4u+g  <-  orig row g*H+u ; also pack W_ih and biases
__global__ void k_permW(const float* __restrict__ Whh, const float* __restrict__ Wih,
                        const float* __restrict__ bih, const float* __restrict__ bhh) {
  int n = blockIdx.x;
  int u = n >> 2, g = n & 3;
  int src = g * HH + u;
  g_Whh[n * HH + threadIdx.x] = Whh[src * HH + threadIdx.x];
  if (threadIdx.x < EE) g_Wih[n * EE + threadIdx.x] = Wih[src * EE + threadIdx.x];
  if (threadIdx.x == 0) g_bias[n] = bih[src] + bhh[src];
}

// xg = obs-rows @ g_Wih^T + g_bias  (4096 x 1024, K=64) tiled GEMM
__global__ void __launch_bounds__(256, 1) k_xg2(const float* __restrict__ obs) {
  __shared__ float As[EE][132];
  __shared__ float Bs[EE][132];
  int bn = blockIdx.x;   // 0..7  (cols)
  int bm = blockIdx.y;   // 0..31 (rows)
  int tid = threadIdx.x;
  for (int e = tid; e < 128 * 16; e += 256) {
    int row = e >> 4, c4 = (e & 15) * 4;
    int gr = bm * 128 + row;
    int t = gr >> 5, b = gr & 31;
    float4 v = *(const float4*)(obs + ((size_t)b * SS + t) * EE + c4);
    As[c4][row] = v.x; As[c4 + 1][row] = v.y; As[c4 + 2][row] = v.z; As[c4 + 3][row] = v.w;
  }
  for (int e = tid; e < 128 * 16; e += 256) {
    int row = e >> 4, c4 = (e & 15) * 4;
    float4 v = *(const float4*)(g_Wih + (size_t)(bn * 128 + row) * EE + c4);
    Bs[c4][row] = v.x; Bs[c4 + 1][row] = v.y; Bs[c4 + 2][row] = v.z; Bs[c4 + 3][row] = v.w;
  }
  __syncthreads();
  int tx = tid & 15, ty = tid >> 4;
  float acc[8][8];
#pragma unroll
  for (int i = 0; i < 8; i++)
#pragma unroll
    for (int j = 0; j < 8; j++) acc[i][j] = 0.0f;
#pragma unroll 8
  for (int kk = 0; kk < EE; kk++) {
    float4 av0 = *(const float4*)&As[kk][ty * 8];
    float4 av1 = *(const float4*)&As[kk][ty * 8 + 4];
    float4 bv0 = *(const float4*)&Bs[kk][tx * 8];
    float4 bv1 = *(const float4*)&Bs[kk][tx * 8 + 4];
    float av[8] = {av0.x, av0.y, av0.z, av0.w, av1.x, av1.y, av1.z, av1.w};
    float bv[8] = {bv0.x, bv0.y, bv0.z, bv0.w, bv1.x, bv1.y, bv1.z, bv1.w};
#pragma unroll
    for (int i = 0; i < 8; i++)
#pragma unroll
      for (int j = 0; j < 8; j++) acc[i][j] = fmaf(av[i], bv[j], acc[i][j]);
  }
  float4 bi0 = *(const float4*)(g_bias + bn * 128 + tx * 8);
  float4 bi1 = *(const float4*)(g_bias + bn * 128 + tx * 8 + 4);
#pragma unroll
  for (int i = 0; i < 8; i++) {
    int gr = bm * 128 + ty * 8 + i;
    float4 v0 = make_float4(acc[i][0] + bi0.x, acc[i][1] + bi0.y, acc[i][2] + bi0.z, acc[i][3] + bi0.w);
    float4 v1 = make_float4(acc[i][4] + bi1.x, acc[i][5] + bi1.y, acc[i][6] + bi1.z, acc[i][7] + bi1.w);
    *(float4*)(g_xg + (size_t)gr * G4 + bn * 128 + tx * 8) = v0;
    *(float4*)(g_xg + (size_t)gr * G4 + bn * 128 + tx * 8 + 4) = v1;
  }
}

// xdot[r] = obs_row(r) . Wobs[:E], warp per row
__global__ void k_xdot(const float* __restrict__ obs, const float* __restrict__ Wobs) {
  int r = blockIdx.x * 8 + (threadIdx.x >> 5);
  int l = threadIdx.x & 31;
  int t = r >> 5, b = r & 31;
  const float* x = obs + ((size_t)b * SS + t) * EE;
  float acc = fmaf(x[l], Wobs[l], x[l + 32] * Wobs[l + 32]);
#pragma unroll
  for (int off = 16; off; off >>= 1) acc += __shfl_xor_sync(0xffffffffu, acc, off);
  if (l == 0) g_xdot[r] = acc;
}

// ---------------- fused GEMM + LSTM cell (packed f32x2 math) ----------------
__global__ void __launch_bounds__(256, 1) k_fused(int t,
    const float* __restrict__ Wobs, const float* __restrict__ Wout) {
  int cur = t & 1, nxt = cur ^ 1;
  __shared__ float As[16][132];
  __shared__ float Bs[16][132];
  __shared__ float s_xgb[BB][132];
  __shared__ int   s_perm[128];
  __shared__ float s_wo[32], s_wu[32];

  int bn = blockIdx.x;       // 0..7  (col block)
  int bm = blockIdx.y;       // 0..15 (row block)
  int tid = threadIdx.x;
  int tx = tid & 15, ty = tid >> 4;
  int lr = tid >> 2;         // 0..63
  int lk = (tid & 3) << 2;   // 0,4,8,12

  if (tid < 128) s_perm[tid] = g_perm[bm * 128 + tid];
  if (tid < 32) {
    s_wo[tid] = Wobs[EE + bn * 32 + tid];
    s_wu[tid] = Wout[bn * 32 + tid];
  }
  {
    const float* src = g_xg + (size_t)(t * BB) * G4 + bn * 128;
    for (int e = tid; e < BB * 128; e += 256) {
      int b = e >> 7, col = e & 127;
      s_xgb[b][col] = src[(size_t)b * G4 + col];
    }
  }
  __syncthreads();

  const float* __restrict__ Acur = g_hbuf[cur];
  const float* Ar0 = Acur + (size_t)s_perm[lr] * HH + lk;
  const float* Ar1 = Acur + (size_t)s_perm[lr + 64] * HH + lk;
  const float* Br0 = g_Whh + (size_t)(bn * 128 + lr) * HH + lk;
  const float* Br1 = g_Whh + (size_t)(bn * 128 + lr + 64) * HH + lk;

  unsigned long long acc2[8][4];
#pragma unroll
  for (int i = 0; i < 8; i++)
#pragma unroll
    for (int j = 0; j < 4; j++) acc2[i][j] = 0ull;

  float4 pa0 = *(const float4*)(Ar0);
  float4 pa1 = *(const float4*)(Ar1);
  float4 pb0 = *(const float4*)(Br0);
  float4 pb1 = *(const float4*)(Br1);

  for (int k0 = 0; k0 < HH; k0 += 16) {
    As[lk + 0][lr] = pa0.x; As[lk + 1][lr] = pa0.y; As[lk + 2][lr] = pa0.z; As[lk + 3][lr] = pa0.w;
    As[lk + 0][lr + 64] = pa1.x; As[lk + 1][lr + 64] = pa1.y; As[lk + 2][lr + 64] = pa1.z; As[lk + 3][lr + 64] = pa1.w;
    Bs[lk + 0][lr] = pb0.x; Bs[lk + 1][lr] = pb0.y; Bs[lk + 2][lr] = pb0.z; Bs[lk + 3][lr] = pb0.w;
    Bs[lk + 0][lr + 64] = pb1.x; Bs[lk + 1][lr + 64] = pb1.y; Bs[lk + 2][lr + 64] = pb1.z; Bs[lk + 3][lr + 64] = pb1.w;
    __syncthreads();
    if (k0 + 16 < HH) {
      pa0 = *(const float4*)(Ar0 + k0 + 16);
      pa1 = *(const float4*)(Ar1 + k0 + 16);
      pb0 = *(const float4*)(Br0 + k0 + 16);
      pb1 = *(const float4*)(Br1 + k0 + 16);
    }
#pragma unroll
    for (int kk = 0; kk < 16; kk++) {
      float4 av0 = *(const float4*)&As[kk][ty * 8];
      float4 av1 = *(const float4*)&As[kk][ty * 8 + 4];
      ulonglong2 bq0 = *(const ulonglong2*)&Bs[kk][tx * 8];
      ulonglong2 bq1 = *(const ulonglong2*)&Bs[kk][tx * 8 + 4];
      float av[8] = {av0.x, av0.y, av0.z, av0.w, av1.x, av1.y, av1.z, av1.w};
#pragma unroll
      for (int i = 0; i < 8; i++) {
        unsigned long long a2 = dup2(av[i]);
        ffma2(acc2[i][0], a2, bq0.x);
        ffma2(acc2[i][1], a2, bq0.y);
        ffma2(acc2[i][2], a2, bq1.x);
        ffma2(acc2[i][3], a2, bq1.y);
      }
    }
    __syncthreads();
  }

  // ---------------- epilogue: LSTM cell + partial dots ----------------
  int ul0 = tx * 2;
  int u0 = bn * 32 + ul0;
  float* __restrict__ Hn = g_hbuf[nxt];
  float* __restrict__ Cn = g_cbuf[nxt];
  const float* __restrict__ Cc = g_cbuf[cur];
  float w_o0 = s_wo[ul0], w_o1 = s_wo[ul0 + 1];
  float w_u0 = s_wu[ul0], w_u1 = s_wu[ul0 + 1];

  float obsr[8], outr[8];
#pragma unroll
  for (int i = 0; i < 8; i++) {
    int lrow = ty * 8 + i;
    int row = bm * 128 + lrow;
    int b = lrow & 31;
    int src = s_perm[lrow];
    float4 xv0 = *(const float4*)&s_xgb[b][tx * 8];
    float4 xv1 = *(const float4*)&s_xgb[b][tx * 8 + 4];
    float2 cold = *(const float2*)(Cc + (size_t)src * HH + u0);
    float a0, a1, a2v, a3, a4, a5, a6, a7;
    unpk2(acc2[i][0], a0, a1);
    unpk2(acc2[i][1], a2v, a3);
    unpk2(acc2[i][2], a4, a5);
    unpk2(acc2[i][3], a6, a7);
    float ig0 = a0 + xv0.x, fg0 = a1 + xv0.y, gg0 = a2v + xv0.z, og0 = a3 + xv0.w;
    float c10 = sigm(fg0) * cold.x + sigm(ig0) * tanhf(gg0);
    float h10 = sigm(og0) * tanhf(c10);
    float ig1 = a4 + xv1.x, fg1 = a5 + xv1.y, gg1 = a6 + xv1.z, og1 = a7 + xv1.w;
    float c11 = sigm(fg1) * cold.y + sigm(ig1) * tanhf(gg1);
    float h11 = sigm(og1) * tanhf(c11);
    *(float2*)(Hn + (size_t)row * HH + u0) = make_float2(h10, h11);
    *(float2*)(Cn + (size_t)row * HH + u0) = make_float2(c10, c11);
    obsr[i] = w_o0 * h10 + w_o1 * h11;
    outr[i] = w_u0 * h10 + w_u1 * h11;
  }
#pragma unroll
  for (int off = 8; off; off >>= 1) {
#pragma unroll
    for (int i = 0; i < 8; i++) {
      obsr[i] += __shfl_xor_sync(0xffffffffu, obsr[i], off);
      outr[i] += __shfl_xor_sync(0xffffffffu, outr[i], off);
    }
  }
  if (tx == 0) {
#pragma unroll
    for (int i = 0; i < 8; i++) {
      int row = bm * 128 + ty * 8 + i;
      g_pobs[bn][row] = obsr[i];
      g_pout[bn][row] = outr[i];
    }
  }
}

// ---------------- per-step resample + outputs ----------------
__global__ void __launch_bounds__(256) k_resample(int t,
    const float* __restrict__ bobs, const float* __restrict__ bout,
    float* __restrict__ out) {
  int b = blockIdx.x;
  int tid = threadIdx.x;
  int w = tid >> 5, l = tid & 31;
  __shared__ float s_dobs[PP], s_dout[PP], s_logits[PP], s_pnew[PP];
  __shared__ int s_idx[PP];

  if (tid < PP) {
    int r = tid * BB + b;
    float so = 0.0f, du = 0.0f;
#pragma unroll
    for (int bn = 0; bn < 8; bn++) { so += g_pobs[bn][r]; du += g_pout[bn][r]; }
    s_dobs[tid] = so; s_dout[tid] = du;
  }
  __syncthreads();

  if (w == 0) {
    float xd = g_xdot[t * BB + b] + bobs[0];
    int pa = l, pb = l + 32;
    float v0 = s_dobs[pa] + xd + g_p[pa * BB + b];
    float v1 = s_dobs[pb] + xd + g_p[pb * BB + b];
    float m = fmaxf(v0, v1);
#pragma unroll
    for (int off = 16; off; off >>= 1) m = fmaxf(m, __shfl_xor_sync(0xffffffffu, m, off));
    float es = expf(v0 - m) + expf(v1 - m);
#pragma unroll
    for (int off = 16; off; off >>= 1) es += __shfl_xor_sync(0xffffffffu, es, off);
    float ls = logf(es);
    float q0 = v0 - m - ls, q1 = v1 - m - ls;
    s_logits[pa] = logf(__fadd_rn(__fmul_rn(ALPHA_F, expf(q0)), CMIX_F));
    s_logits[pb] = logf(__fadd_rn(__fmul_rn(ALPHA_F, expf(q1)), CMIX_F));
  }
  __syncthreads();

  uint2 sub = g_sub[t];
  for (int i = w; i < PP; i += 8) {
    uint32_t base = (uint32_t)(i * NL + b * PP);
    float g0 = gumbel_from(sub.x, sub.y, base + (uint32_t)l) + s_logits[l];
    float g1 = gumbel_from(sub.x, sub.y, base + (uint32_t)(l + 32)) + s_logits[l + 32];
    float best = g0; int bi = l;
    if (g1 > best) { best = g1; bi = l + 32; }
#pragma unroll
    for (int off = 16; off; off >>= 1) {
      float ov = __shfl_xor_sync(0xffffffffu, best, off);
      int oi = __shfl_xor_sync(0xffffffffu, bi, off);
      if (ov > best || (ov == best && oi < bi)) { best = ov; bi = oi; }
    }
    if (l == 0) s_idx[i] = bi;
  }
  __syncthreads();

  if (w == 0) {
    float lw0 = s_logits[s_idx[l]];
    float lw1 = s_logits[s_idx[l + 32]];
    float m2 = fmaxf(lw0, lw1);
#pragma unroll
    for (int off = 16; off; off >>= 1) m2 = fmaxf(m2, __shfl_xor_sync(0xffffffffu, m2, off));
    float es = expf(lw0 - m2) + expf(lw1 - m2);
#pragma unroll
    for (int off = 16; off; off >>= 1) es += __shfl_xor_sync(0xffffffffu, es, off);
    float ls2 = logf(es);
    float pn0 = lw0 - m2 - ls2, pn1 = lw1 - m2 - ls2;
    s_pnew[l] = pn0; s_pnew[l + 32] = pn1;
    float yl = expf(pn0) * s_dout[s_idx[l]] + expf(pn1) * s_dout[s_idx[l + 32]];
#pragma unroll
    for (int off = 16; off; off >>= 1) yl += __shfl_xor_sync(0xffffffffu, yl, off);
    if (l == 0) out[t * BB + b] = lrelu(yl + bout[0]);
  }
  __syncthreads();

  if (tid < PP) {
    int i = tid;
    float d = s_dout[s_idx[i]] + bout[0];
    out[SS * BB + (size_t)t * NL + i * BB + b] = lrelu(d);
    g_p[i * BB + b] = s_pnew[i];
    g_perm[i * BB + b] = s_idx[i] * BB + b;
  }
}

// ---------------- launch ----------------
extern "C" void kernel_launch(void* const* d_in, const int* in_sizes, int n_in,
                              void* d_out, int out_size) {
  const float* obs  = (const float*)d_in[0];
  const float* h0   = (const float*)d_in[1];
  const float* c0   = (const float*)d_in[2];
  const float* Wih  = (const float*)d_in[3];
  const float* bih  = (const float*)d_in[4];
  const float* Whh  = (const float*)d_in[5];
  const float* bhh  = (const float*)d_in[6];
  const float* Wobs = (const float*)d_in[7];
  const float* bobs = (const float*)d_in[8];
  const float* Wout = (const float*)d_in[9];
  const float* bout = (const float*)d_in[10];
  float* out = (float*)d_out;

  k_prep_keys<<<1, 1>>>();
  k_init<<<(NL * HH + 255) / 256, 256>>>(h0, c0);
  k_permW<<<G4, HH>>>(Whh, Wih, bih, bhh);
  k_xg2<<<dim3(8, 32), 256>>>(obs);
  k_xdot<<<SS * BB / 8, 256>>>(obs, Wobs);

  for (int t = 0; t < SS; t++) {
    k_fused<<<dim3(8, 16), 256>>>(t, Wobs, Wout);
    k_resample<<<BB, 256>>>(t, bobs, bout, out);
  }
  (void)in_sizes; (void)n_in; (void)out_size;
}

// round 4
// speedup vs baseline: 2.3417x; 1.0276x over previous
#include <cuda_runtime.h>
#include <cstdint>

// Problem constants
#define PP 64     // particles
#define HH 256    // hidden
#define EE 64     // input size
#define BB 32     // batch
#define SS 128    // seq len
#define G4 1024   // 4*H
#define NL 2048   // PP*BB lanes
#define NCTA 128  // persistent grid

#define ALPHA_F 0.1f
#define CMIX_F  0.0140625f         // (1-alpha)/P
#define TINY_F  1.17549435e-38f    // float32 tiny (smallest normal)

// ---------------- device scratch (no allocations allowed) ----------------
__device__ float g_xg[SS * BB * G4];   // x@W_ih^T + biases, PERMUTED gate layout (col 4u+g)
__device__ float g_xdot[SS * BB];      // x . W_obs[:E]
__device__ float g_Whh[G4 * HH];       // W_hh rows permuted: row 4u+g = orig row g*H+u
__device__ float g_Wih[G4 * EE];       // W_ih rows permuted likewise
__device__ float g_bias[G4];           // b_ih + b_hh, permuted
__device__ float g_hbuf[2][NL * HH];   // ping-pong pre-resample h state
__device__ float g_cbuf[2][NL * HH];   // ping-pong pre-resample c state
__device__ int   g_perm[NL];           // resampling permutation (row -> source row)
__device__ float g_p[NL];              // log weights
__device__ float g_pobs[8][NL];        // partial obs dots per N-block
__device__ float g_pout[8][NL];        // partial out dots per N-block
__device__ uint2 g_sub[SS];            // per-step subkeys
__device__ unsigned int g_barc;        // barrier arrive counter (zero-init)
__device__ unsigned int g_barg;        // barrier generation (zero-init)

// ---------------- packed f32x2 helpers ----------------
__device__ __forceinline__ void ffma2(unsigned long long& d, unsigned long long a,
                                      unsigned long long b) {
  asm("fma.rn.f32x2 %0, %1, %2, %0;" : "+l"(d) : "l"(a), "l"(b));
}
__device__ __forceinline__ unsigned long long dup2(float a) {
  unsigned long long r;
  asm("mov.b64 %0, {%1, %1};" : "=l"(r) : "f"(a));
  return r;
}
__device__ __forceinline__ void unpk2(unsigned long long v, float& lo, float& hi) {
  asm("mov.b64 {%0, %1}, %2;" : "=f"(lo), "=f"(hi) : "l"(v));
}

// ---------------- grid-wide barrier (all NCTA CTAs resident: 128 <= 148 SMs) ----------------
__device__ __forceinline__ void grid_sync() {
  __syncthreads();
  if (threadIdx.x == 0) {
    __threadfence();
    unsigned int gen = *(volatile unsigned int*)&g_barg;
    if (atomicAdd(&g_barc, 1u) == NCTA - 1u) {
      atomicExch(&g_barc, 0u);
      __threadfence();
      atomicAdd(&g_barg, 1u);
    } else {
      while (*(volatile unsigned int*)&g_barg == gen) { __nanosleep(64); }
    }
    __threadfence();
  }
  __syncthreads();
}

// ---------------- threefry2x32 (JAX-compatible) ----------------
__device__ __forceinline__ void tf2x32(uint32_t k0, uint32_t k1,
                                       uint32_t x0, uint32_t x1,
                                       uint32_t& o0, uint32_t& o1) {
  uint32_t ks2 = k0 ^ k1 ^ 0x1BD11BDAu;
  x0 += k0; x1 += k1;
#define TFR(r) { x0 += x1; x1 = (x1 << (r)) | (x1 >> (32 - (r))); x1 ^= x0; }
  TFR(13) TFR(15) TFR(26) TFR(6)   x0 += k1;  x1 += ks2 + 1u;
  TFR(17) TFR(29) TFR(16) TFR(24)  x0 += ks2; x1 += k0  + 2u;
  TFR(13) TFR(15) TFR(26) TFR(6)   x0 += k0;  x1 += k1  + 3u;
  TFR(17) TFR(29) TFR(16) TFR(24)  x0 += k1;  x1 += ks2 + 4u;
  TFR(13) TFR(15) TFR(26) TFR(6)   x0 += ks2; x1 += k0  + 5u;
#undef TFR
  o0 = x0; o1 = x1;
}

__device__ __forceinline__ float gumbel_from(uint32_t k0, uint32_t k1, uint32_t flat) {
  uint32_t o0, o1;
  tf2x32(k0, k1, 0u, flat, o0, o1);
  uint32_t bits = o0 ^ o1;
  float f = __uint_as_float((bits >> 9) | 0x3F800000u) - 1.0f;  // [0,1)
  f = fmaxf(f, TINY_F);
  return -logf(-logf(f));
}

__device__ __forceinline__ float sigm(float x) { return 1.0f / (1.0f + expf(-x)); }
__device__ __forceinline__ float lrelu(float x) { return x >= 0.0f ? x : 0.01f * x; }

// ---------------- prologue kernels ----------------
__global__ void k_prep_keys() {
  if (threadIdx.x == 0 && blockIdx.x == 0) {
    uint32_t k0 = 0u, k1 = 42u;
    for (int t = 0; t < SS; t++) {
      uint32_t n0, n1, s0, s1;
      tf2x32(k0, k1, 0u, 0u, n0, n1);
      tf2x32(k0, k1, 0u, 1u, s0, s1);
      g_sub[t] = make_uint2(s0, s1);
      k0 = n0; k1 = n1;
    }
  }
}

__global__ void k_init(const float* __restrict__ h0, const float* __restrict__ c0) {
  int i = blockIdx.x * blockDim.x + threadIdx.x;
  if (i < NL * HH) { g_hbuf[0][i] = h0[i]; g_cbuf[0][i] = c0[i]; }
  if (i < NL) { g_p[i] = (float)(-4.158883083359672); g_perm[i] = i; }
}

__global__ void k_permW(const float* __restrict__ Whh, const float* __restrict__ Wih,
                        const float* __restrict__ bih, const float* __restrict__ bhh) {
  int n = blockIdx.x;
  int u = n >> 2, g = n & 3;
  int src = g * HH + u;
  g_Whh[n * HH + threadIdx.x] = Whh[src * HH + threadIdx.x];
  if (threadIdx.x < EE) g_Wih[n * EE + threadIdx.x] = Wih[src * EE + threadIdx.x];
  if (threadIdx.x == 0) g_bias[n] = bih[src] + bhh[src];
}

// xg = obs-rows @ g_Wih^T + g_bias  (4096 x 1024, K=64) tiled GEMM
__global__ void __launch_bounds__(256, 1) k_xg2(const float* __restrict__ obs) {
  __shared__ float As[EE][132];
  __shared__ float Bs[EE][132];
  int bn = blockIdx.x;
  int bm = blockIdx.y;
  int tid = threadIdx.x;
  for (int e = tid; e < 128 * 16; e += 256) {
    int row = e >> 4, c4 = (e & 15) * 4;
    int gr = bm * 128 + row;
    int t = gr >> 5, b = gr & 31;
    float4 v = *(const float4*)(obs + ((size_t)b * SS + t) * EE + c4);
    As[c4][row] = v.x; As[c4 + 1][row] = v.y; As[c4 + 2][row] = v.z; As[c4 + 3][row] = v.w;
  }
  for (int e = tid; e < 128 * 16; e += 256) {
    int row = e >> 4, c4 = (e & 15) * 4;
    float4 v = *(const float4*)(g_Wih + (size_t)(bn * 128 + row) * EE + c4);
    Bs[c4][row] = v.x; Bs[c4 + 1][row] = v.y; Bs[c4 + 2][row] = v.z; Bs[c4 + 3][row] = v.w;
  }
  __syncthreads();
  int tx = tid & 15, ty = tid >> 4;
  float acc[8][8];
#pragma unroll
  for (int i = 0; i < 8; i++)
#pragma unroll
    for (int j = 0; j < 8; j++) acc[i][j] = 0.0f;
#pragma unroll 8
  for (int kk = 0; kk < EE; kk++) {
    float4 av0 = *(const float4*)&As[kk][ty * 8];
    float4 av1 = *(const float4*)&As[kk][ty * 8 + 4];
    float4 bv0 = *(const float4*)&Bs[kk][tx * 8];
    float4 bv1 = *(const float4*)&Bs[kk][tx * 8 + 4];
    float av[8] = {av0.x, av0.y, av0.z, av0.w, av1.x, av1.y, av1.z, av1.w};
    float bv[8] = {bv0.x, bv0.y, bv0.z, bv0.w, bv1.x, bv1.y, bv1.z, bv1.w};
#pragma unroll
    for (int i = 0; i < 8; i++)
#pragma unroll
      for (int j = 0; j < 8; j++) acc[i][j] = fmaf(av[i], bv[j], acc[i][j]);
  }
  float4 bi0 = *(const float4*)(g_bias + bn * 128 + tx * 8);
  float4 bi1 = *(const float4*)(g_bias + bn * 128 + tx * 8 + 4);
#pragma unroll
  for (int i = 0; i < 8; i++) {
    int gr = bm * 128 + ty * 8 + i;
    float4 v0 = make_float4(acc[i][0] + bi0.x, acc[i][1] + bi0.y, acc[i][2] + bi0.z, acc[i][3] + bi0.w);
    float4 v1 = make_float4(acc[i][4] + bi1.x, acc[i][5] + bi1.y, acc[i][6] + bi1.z, acc[i][7] + bi1.w);
    *(float4*)(g_xg + (size_t)gr * G4 + bn * 128 + tx * 8) = v0;
    *(float4*)(g_xg + (size_t)gr * G4 + bn * 128 + tx * 8 + 4) = v1;
  }
}

__global__ void k_xdot(const float* __restrict__ obs, const float* __restrict__ Wobs) {
  int r = blockIdx.x * 8 + (threadIdx.x >> 5);
  int l = threadIdx.x & 31;
  int t = r >> 5, b = r & 31;
  const float* x = obs + ((size_t)b * SS + t) * EE;
  float acc = fmaf(x[l], Wobs[l], x[l + 32] * Wobs[l + 32]);
#pragma unroll
  for (int off = 16; off; off >>= 1) acc += __shfl_xor_sync(0xffffffffu, acc, off);
  if (l == 0) g_xdot[r] = acc;
}

// ---------------- persistent main kernel: full time loop ----------------
__global__ void __launch_bounds__(256, 1) k_main(
    const float* __restrict__ Wobs, const float* __restrict__ bobs,
    const float* __restrict__ Wout, const float* __restrict__ bout,
    float* __restrict__ out) {
  __shared__ float As[16][132];
  __shared__ float Bs[16][132];
  __shared__ float s_xgb[BB][132];
  __shared__ int   s_perm[128];
  __shared__ float s_wo[32], s_wu[32];
  __shared__ float s_dobs[PP], s_dout[PP], s_logits[PP], s_pnew[PP];
  __shared__ int   s_idx[PP];

  int bx = blockIdx.x;
  int bn = bx & 7;           // col block 0..7
  int bm = bx >> 3;          // row block 0..15
  int tid = threadIdx.x;
  int tx = tid & 15, ty = tid >> 4;
  int lr = tid >> 2;
  int lk = (tid & 3) << 2;
  int w = tid >> 5, l = tid & 31;

  if (tid < 32) {
    s_wo[tid] = Wobs[EE + bn * 32 + tid];
    s_wu[tid] = Wout[bn * 32 + tid];
  }
  float bobs0 = bobs[0], bout0 = bout[0];

  const float* Br0 = g_Whh + (size_t)(bn * 128 + lr) * HH + lk;
  const float* Br1 = g_Whh + (size_t)(bn * 128 + lr + 64) * HH + lk;

  for (int t = 0; t < SS; t++) {
    int cur = t & 1, nxt = cur ^ 1;

    // load permutation (cross-CTA data -> L2) and xg slice (read-only, pre-kernel)
    if (tid < 128) s_perm[tid] = __ldcg(&g_perm[bm * 128 + tid]);
    {
      const float* src = g_xg + (size_t)(t * BB) * G4 + bn * 128;
      for (int e = tid; e < BB * 128; e += 256) {
        int b = e >> 7, col = e & 127;
        s_xgb[b][col] = src[(size_t)b * G4 + col];
      }
    }
    __syncthreads();

    const float* __restrict__ Acur = g_hbuf[cur];
    const float* Ar0 = Acur + (size_t)s_perm[lr] * HH + lk;
    const float* Ar1 = Acur + (size_t)s_perm[lr + 64] * HH + lk;

    unsigned long long acc2[8][4];
#pragma unroll
    for (int i = 0; i < 8; i++)
#pragma unroll
      for (int j = 0; j < 4; j++) acc2[i][j] = 0ull;

    // A/C state is written by other CTAs within this launch -> bypass L1 (.cg)
    float4 pa0 = __ldcg((const float4*)(Ar0));
    float4 pa1 = __ldcg((const float4*)(Ar1));
    float4 pb0 = *(const float4*)(Br0);
    float4 pb1 = *(const float4*)(Br1);

    for (int k0 = 0; k0 < HH; k0 += 16) {
      As[lk + 0][lr] = pa0.x; As[lk + 1][lr] = pa0.y; As[lk + 2][lr] = pa0.z; As[lk + 3][lr] = pa0.w;
      As[lk + 0][lr + 64] = pa1.x; As[lk + 1][lr + 64] = pa1.y; As[lk + 2][lr + 64] = pa1.z; As[lk + 3][lr + 64] = pa1.w;
      Bs[lk + 0][lr] = pb0.x; Bs[lk + 1][lr] = pb0.y; Bs[lk + 2][lr] = pb0.z; Bs[lk + 3][lr] = pb0.w;
      Bs[lk + 0][lr + 64] = pb1.x; Bs[lk + 1][lr + 64] = pb1.y; Bs[lk + 2][lr + 64] = pb1.z; Bs[lk + 3][lr + 64] = pb1.w;
      __syncthreads();
      if (k0 + 16 < HH) {
        pa0 = __ldcg((const float4*)(Ar0 + k0 + 16));
        pa1 = __ldcg((const float4*)(Ar1 + k0 + 16));
        pb0 = *(const float4*)(Br0 + k0 + 16);
        pb1 = *(const float4*)(Br1 + k0 + 16);
      }
#pragma unroll
      for (int kk = 0; kk < 16; kk++) {
        float4 av0 = *(const float4*)&As[kk][ty * 8];
        float4 av1 = *(const float4*)&As[kk][ty * 8 + 4];
        ulonglong2 bq0 = *(const ulonglong2*)&Bs[kk][tx * 8];
        ulonglong2 bq1 = *(const ulonglong2*)&Bs[kk][tx * 8 + 4];
        float av[8] = {av0.x, av0.y, av0.z, av0.w, av1.x, av1.y, av1.z, av1.w};
#pragma unroll
        for (int i = 0; i < 8; i++) {
          unsigned long long a2 = dup2(av[i]);
          ffma2(acc2[i][0], a2, bq0.x);
          ffma2(acc2[i][1], a2, bq0.y);
          ffma2(acc2[i][2], a2, bq1.x);
          ffma2(acc2[i][3], a2, bq1.y);
        }
      }
      __syncthreads();
    }

    // epilogue: LSTM cell + partial dots
    {
      int ul0 = tx * 2;
      int u0 = bn * 32 + ul0;
      float* __restrict__ Hn = g_hbuf[nxt];
      float* __restrict__ Cn = g_cbuf[nxt];
      const float* __restrict__ Cc = g_cbuf[cur];
      float w_o0 = s_wo[ul0], w_o1 = s_wo[ul0 + 1];
      float w_u0 = s_wu[ul0], w_u1 = s_wu[ul0 + 1];

      float obsr[8], outr[8];
#pragma unroll
      for (int i = 0; i < 8; i++) {
        int lrow = ty * 8 + i;
        int row = bm * 128 + lrow;
        int b = lrow & 31;
        int src = s_perm[lrow];
        float4 xv0 = *(const float4*)&s_xgb[b][tx * 8];
        float4 xv1 = *(const float4*)&s_xgb[b][tx * 8 + 4];
        float2 cold = __ldcg((const float2*)(Cc + (size_t)src * HH + u0));
        float a0, a1, a2v, a3, a4, a5, a6, a7;
        unpk2(acc2[i][0], a0, a1);
        unpk2(acc2[i][1], a2v, a3);
        unpk2(acc2[i][2], a4, a5);
        unpk2(acc2[i][3], a6, a7);
        float ig0 = a0 + xv0.x, fg0 = a1 + xv0.y, gg0 = a2v + xv0.z, og0 = a3 + xv0.w;
        float c10 = sigm(fg0) * cold.x + sigm(ig0) * tanhf(gg0);
        float h10 = sigm(og0) * tanhf(c10);
        float ig1 = a4 + xv1.x, fg1 = a5 + xv1.y, gg1 = a6 + xv1.z, og1 = a7 + xv1.w;
        float c11 = sigm(fg1) * cold.y + sigm(ig1) * tanhf(gg1);
        float h11 = sigm(og1) * tanhf(c11);
        *(float2*)(Hn + (size_t)row * HH + u0) = make_float2(h10, h11);
        *(float2*)(Cn + (size_t)row * HH + u0) = make_float2(c10, c11);
        obsr[i] = w_o0 * h10 + w_o1 * h11;
        outr[i] = w_u0 * h10 + w_u1 * h11;
      }
#pragma unroll
      for (int off = 8; off; off >>= 1) {
#pragma unroll
        for (int i = 0; i < 8; i++) {
          obsr[i] += __shfl_xor_sync(0xffffffffu, obsr[i], off);
          outr[i] += __shfl_xor_sync(0xffffffffu, outr[i], off);
        }
      }
      if (tx == 0) {
#pragma unroll
        for (int i = 0; i < 8; i++) {
          int row = bm * 128 + ty * 8 + i;
          g_pobs[bn][row] = obsr[i];
          g_pout[bn][row] = outr[i];
        }
      }
    }

    grid_sync();   // partials + new h/c visible grid-wide

    // ------------- resample: CTAs 0..31, one per batch -------------
    if (bx < BB) {
      int b = bx;
      if (tid < PP) {
        int r = tid * BB + b;
        float so = 0.0f, du = 0.0f;
#pragma unroll
        for (int nb = 0; nb < 8; nb++) {
          so += __ldcg(&g_pobs[nb][r]);
          du += __ldcg(&g_pout[nb][r]);
        }
        s_dobs[tid] = so; s_dout[tid] = du;
      }
      __syncthreads();

      if (w == 0) {
        float xd = g_xdot[t * BB + b] + bobs0;
        float v0 = s_dobs[l] + xd + __ldcg(&g_p[l * BB + b]);
        float v1 = s_dobs[l + 32] + xd + __ldcg(&g_p[(l + 32) * BB + b]);
        float m = fmaxf(v0, v1);
#pragma unroll
        for (int off = 16; off; off >>= 1) m = fmaxf(m, __shfl_xor_sync(0xffffffffu, m, off));
        float es = expf(v0 - m) + expf(v1 - m);
#pragma unroll
        for (int off = 16; off; off >>= 1) es += __shfl_xor_sync(0xffffffffu, es, off);
        float ls = logf(es);
        float q0 = v0 - m - ls, q1 = v1 - m - ls;
        s_logits[l] = logf(__fadd_rn(__fmul_rn(ALPHA_F, expf(q0)), CMIX_F));
        s_logits[l + 32] = logf(__fadd_rn(__fmul_rn(ALPHA_F, expf(q1)), CMIX_F));
      }
      __syncthreads();

      uint2 sub = g_sub[t];
      for (int i = w; i < PP; i += 8) {
        uint32_t base = (uint32_t)(i * NL + b * PP);
        float g0 = gumbel_from(sub.x, sub.y, base + (uint32_t)l) + s_logits[l];
        float g1 = gumbel_from(sub.x, sub.y, base + (uint32_t)(l + 32)) + s_logits[l + 32];
        float best = g0; int bi = l;
        if (g1 > best) { best = g1; bi = l + 32; }
#pragma unroll
        for (int off = 16; off; off >>= 1) {
          float ov = __shfl_xor_sync(0xffffffffu, best, off);
          int oi = __shfl_xor_sync(0xffffffffu, bi, off);
          if (ov > best || (ov == best && oi < bi)) { best = ov; bi = oi; }
        }
        if (l == 0) s_idx[i] = bi;
      }
      __syncthreads();

      if (w == 0) {
        float lw0 = s_logits[s_idx[l]];
        float lw1 = s_logits[s_idx[l + 32]];
        float m2 = fmaxf(lw0, lw1);
#pragma unroll
        for (int off = 16; off; off >>= 1) m2 = fmaxf(m2, __shfl_xor_sync(0xffffffffu, m2, off));
        float es = expf(lw0 - m2) + expf(lw1 - m2);
#pragma unroll
        for (int off = 16; off; off >>= 1) es += __shfl_xor_sync(0xffffffffu, es, off);
        float ls2 = logf(es);
        float pn0 = lw0 - m2 - ls2, pn1 = lw1 - m2 - ls2;
        s_pnew[l] = pn0; s_pnew[l + 32] = pn1;
        float yl = expf(pn0) * s_dout[s_idx[l]] + expf(pn1) * s_dout[s_idx[l + 32]];
#pragma unroll
        for (int off = 16; off; off >>= 1) yl += __shfl_xor_sync(0xffffffffu, yl, off);
        if (l == 0) out[t * BB + b] = lrelu(yl + bout0);
      }
      __syncthreads();

      if (tid < PP) {
        int i = tid;
        float d = s_dout[s_idx[i]] + bout0;
        out[SS * BB + (size_t)t * NL + i * BB + b] = lrelu(d);
        g_p[i * BB + b] = s_pnew[i];
        g_perm[i * BB + b] = s_idx[i] * BB + b;
      }
    }

    grid_sync();   // perm + p visible before next step's GEMM
  }
}

// ---------------- launch ----------------
extern "C" void kernel_launch(void* const* d_in, const int* in_sizes, int n_in,
                              void* d_out, int out_size) {
  const float* obs  = (const float*)d_in[0];
  const float* h0   = (const float*)d_in[1];
  const float* c0   = (const float*)d_in[2];
  const float* Wih  = (const float*)d_in[3];
  const float* bih  = (const float*)d_in[4];
  const float* Whh  = (const float*)d_in[5];
  const float* bhh  = (const float*)d_in[6];
  const float* Wobs = (const float*)d_in[7];
  const float* bobs = (const float*)d_in[8];
  const float* Wout = (const float*)d_in[9];
  const float* bout = (const float*)d_in[10];
  float* out = (float*)d_out;

  k_prep_keys<<<1, 1>>>();
  k_init<<<(NL * HH + 255) / 256, 256>>>(h0, c0);
  k_permW<<<G4, HH>>>(Whh, Wih, bih, bhh);
  k_xg2<<<dim3(8, 32), 256>>>(obs);
  k_xdot<<<SS * BB / 8, 256>>>(obs, Wobs);
  k_main<<<NCTA, 256>>>(Wobs, bobs, Wout, bout, out);
  (void)in_sizes; (void)n_in; (void)out_size;
}

// round 5
// speedup vs baseline: 2.3470x; 1.0023x over previous
#include <cuda_runtime.h>
#include <cstdint>

// Problem constants
#define PP 64     // particles
#define HH 256    // hidden
#define EE 64     // input size
#define BB 32     // batch
#define SS 128    // seq len
#define G4 1024   // 4*H
#define NL 2048   // PP*BB lanes
#define NCTA 128  // persistent grid

#define ALPHA_F 0.1f
#define CMIX_F  0.0140625f         // (1-alpha)/P
#define TINY_F  1.17549435e-38f    // float32 tiny (smallest normal)

// ---------------- device scratch (no allocations allowed) ----------------
__device__ float g_xg[SS * BB * G4];   // x@W_ih^T + biases, PERMUTED gate layout (col 4u+g)
__device__ float g_xdot[SS * BB];      // x . W_obs[:E]
__device__ float g_Whh[G4 * HH];       // W_hh rows permuted: row 4u+g = orig row g*H+u
__device__ float g_Wih[G4 * EE];       // W_ih rows permuted likewise
__device__ float g_bias[G4];           // b_ih + b_hh, permuted
__device__ float g_hbuf[2][NL * HH];   // ping-pong pre-resample h state
__device__ float g_cbuf[2][NL * HH];   // ping-pong pre-resample c state
__device__ int   g_perm[NL];           // resampling permutation (row -> source row)
__device__ float g_p[NL];              // log weights
__device__ float g_pobs[8][NL];        // partial obs dots per N-block
__device__ float g_pout[8][NL];        // partial out dots per N-block
__device__ uint2 g_sub[SS];            // per-step subkeys
__device__ unsigned int g_barc;        // barrier arrive counter (zero-init)
__device__ unsigned int g_barg;        // barrier generation (zero-init)

// ---------------- packed f32x2 helpers ----------------
__device__ __forceinline__ void ffma2(unsigned long long& d, unsigned long long a,
                                      unsigned long long b) {
  asm("fma.rn.f32x2 %0, %1, %2, %0;" : "+l"(d) : "l"(a), "l"(b));
}
__device__ __forceinline__ unsigned long long dup2(float a) {
  unsigned long long r;
  asm("mov.b64 %0, {%1, %1};" : "=l"(r) : "f"(a));
  return r;
}
__device__ __forceinline__ void unpk2(unsigned long long v, float& lo, float& hi) {
  asm("mov.b64 {%0, %1}, %2;" : "=f"(lo), "=f"(hi) : "l"(v));
}

// ---------------- grid-wide barrier (all NCTA CTAs resident: 128 <= 148 SMs) ----------------
__device__ __forceinline__ void grid_sync() {
  __syncthreads();
  if (threadIdx.x == 0) {
    __threadfence();
    unsigned int gen = *(volatile unsigned int*)&g_barg;
    if (atomicAdd(&g_barc, 1u) == NCTA - 1u) {
      atomicExch(&g_barc, 0u);
      __threadfence();
      atomicAdd(&g_barg, 1u);
    } else {
      while (*(volatile unsigned int*)&g_barg == gen) { __nanosleep(64); }
    }
    __threadfence();
  }
  __syncthreads();
}

// ---------------- threefry2x32 (JAX-compatible) ----------------
__device__ __forceinline__ void tf2x32(uint32_t k0, uint32_t k1,
                                       uint32_t x0, uint32_t x1,
                                       uint32_t& o0, uint32_t& o1) {
  uint32_t ks2 = k0 ^ k1 ^ 0x1BD11BDAu;
  x0 += k0; x1 += k1;
#define TFR(r) { x0 += x1; x1 = (x1 << (r)) | (x1 >> (32 - (r))); x1 ^= x0; }
  TFR(13) TFR(15) TFR(26) TFR(6)   x0 += k1;  x1 += ks2 + 1u;
  TFR(17) TFR(29) TFR(16) TFR(24)  x0 += ks2; x1 += k0  + 2u;
  TFR(13) TFR(15) TFR(26) TFR(6)   x0 += k0;  x1 += k1  + 3u;
  TFR(17) TFR(29) TFR(16) TFR(24)  x0 += k1;  x1 += ks2 + 4u;
  TFR(13) TFR(15) TFR(26) TFR(6)   x0 += ks2; x1 += k0  + 5u;
#undef TFR
  o0 = x0; o1 = x1;
}

__device__ __forceinline__ float gumbel_from(uint32_t k0, uint32_t k1, uint32_t flat) {
  uint32_t o0, o1;
  tf2x32(k0, k1, 0u, flat, o0, o1);
  uint32_t bits = o0 ^ o1;
  float f = __uint_as_float((bits >> 9) | 0x3F800000u) - 1.0f;  // [0,1)
  f = fmaxf(f, TINY_F);
  return -logf(-logf(f));
}

__device__ __forceinline__ float sigm(float x) { return 1.0f / (1.0f + expf(-x)); }
__device__ __forceinline__ float lrelu(float x) { return x >= 0.0f ? x : 0.01f * x; }

// ---------------- prologue kernels ----------------
__global__ void k_prep_keys() {
  if (threadIdx.x == 0 && blockIdx.x == 0) {
    uint32_t k0 = 0u, k1 = 42u;
    for (int t = 0; t < SS; t++) {
      uint32_t n0, n1, s0, s1;
      tf2x32(k0, k1, 0u, 0u, n0, n1);
      tf2x32(k0, k1, 0u, 1u, s0, s1);
      g_sub[t] = make_uint2(s0, s1);
      k0 = n0; k1 = n1;
    }
  }
}

__global__ void k_init(const float* __restrict__ h0, const float* __restrict__ c0) {
  int i = blockIdx.x * blockDim.x + threadIdx.x;
  if (i < NL * HH) { g_hbuf[0][i] = h0[i]; g_cbuf[0][i] = c0[i]; }
  if (i < NL) { g_p[i] = (float)(-4.158883083359672); g_perm[i] = i; }
}

__global__ void k_permW(const float* __restrict__ Whh, const float* __restrict__ Wih,
                        const float* __restrict__ bih, const float* __restrict__ bhh) {
  int n = blockIdx.x;
  int u = n >> 2, g = n & 3;
  int src = g * HH + u;
  g_Whh[n * HH + threadIdx.x] = Whh[src * HH + threadIdx.x];
  if (threadIdx.x < EE) g_Wih[n * EE + threadIdx.x] = Wih[src * EE + threadIdx.x];
  if (threadIdx.x == 0) g_bias[n] = bih[src] + bhh[src];
}

// xg = obs-rows @ g_Wih^T + g_bias  (4096 x 1024, K=64) tiled GEMM
__global__ void __launch_bounds__(256, 1) k_xg2(const float* __restrict__ obs) {
  __shared__ float As[EE][132];
  __shared__ float Bs[EE][132];
  int bn = blockIdx.x;
  int bm = blockIdx.y;
  int tid = threadIdx.x;
  for (int e = tid; e < 128 * 16; e += 256) {
    int row = e >> 4, c4 = (e & 15) * 4;
    int gr = bm * 128 + row;
    int t = gr >> 5, b = gr & 31;
    float4 v = *(const float4*)(obs + ((size_t)b * SS + t) * EE + c4);
    As[c4][row] = v.x; As[c4 + 1][row] = v.y; As[c4 + 2][row] = v.z; As[c4 + 3][row] = v.w;
  }
  for (int e = tid; e < 128 * 16; e += 256) {
    int row = e >> 4, c4 = (e & 15) * 4;
    float4 v = *(const float4*)(g_Wih + (size_t)(bn * 128 + row) * EE + c4);
    Bs[c4][row] = v.x; Bs[c4 + 1][row] = v.y; Bs[c4 + 2][row] = v.z; Bs[c4 + 3][row] = v.w;
  }
  __syncthreads();
  int tx = tid & 15, ty = tid >> 4;
  float acc[8][8];
#pragma unroll
  for (int i = 0; i < 8; i++)
#pragma unroll
    for (int j = 0; j < 8; j++) acc[i][j] = 0.0f;
#pragma unroll 8
  for (int kk = 0; kk < EE; kk++) {
    float4 av0 = *(const float4*)&As[kk][ty * 8];
    float4 av1 = *(const float4*)&As[kk][ty * 8 + 4];
    float4 bv0 = *(const float4*)&Bs[kk][tx * 8];
    float4 bv1 = *(const float4*)&Bs[kk][tx * 8 + 4];
    float av[8] = {av0.x, av0.y, av0.z, av0.w, av1.x, av1.y, av1.z, av1.w};
    float bv[8] = {bv0.x, bv0.y, bv0.z, bv0.w, bv1.x, bv1.y, bv1.z, bv1.w};
#pragma unroll
    for (int i = 0; i < 8; i++)
#pragma unroll
      for (int j = 0; j < 8; j++) acc[i][j] = fmaf(av[i], bv[j], acc[i][j]);
  }
  float4 bi0 = *(const float4*)(g_bias + bn * 128 + tx * 8);
  float4 bi1 = *(const float4*)(g_bias + bn * 128 + tx * 8 + 4);
#pragma unroll
  for (int i = 0; i < 8; i++) {
    int gr = bm * 128 + ty * 8 + i;
    float4 v0 = make_float4(acc[i][0] + bi0.x, acc[i][1] + bi0.y, acc[i][2] + bi0.z, acc[i][3] + bi0.w);
    float4 v1 = make_float4(acc[i][4] + bi1.x, acc[i][5] + bi1.y, acc[i][6] + bi1.z, acc[i][7] + bi1.w);
    *(float4*)(g_xg + (size_t)gr * G4 + bn * 128 + tx * 8) = v0;
    *(float4*)(g_xg + (size_t)gr * G4 + bn * 128 + tx * 8 + 4) = v1;
  }
}

__global__ void k_xdot(const float* __restrict__ obs, const float* __restrict__ Wobs) {
  int r = blockIdx.x * 8 + (threadIdx.x >> 5);
  int l = threadIdx.x & 31;
  int t = r >> 5, b = r & 31;
  const float* x = obs + ((size_t)b * SS + t) * EE;
  float acc = fmaf(x[l], Wobs[l], x[l + 32] * Wobs[l + 32]);
#pragma unroll
  for (int off = 16; off; off >>= 1) acc += __shfl_xor_sync(0xffffffffu, acc, off);
  if (l == 0) g_xdot[r] = acc;
}

// ---------------- persistent main kernel: full time loop ----------------
__global__ void __launch_bounds__(256, 1) k_main(
    const float* __restrict__ Wobs, const float* __restrict__ bobs,
    const float* __restrict__ Wout, const float* __restrict__ bout,
    float* __restrict__ out) {
  __shared__ float As[16][132];
  __shared__ float Bs[16][132];
  __shared__ float s_xgb[BB][132];
  __shared__ int   s_perm[128];
  __shared__ float s_wo[32], s_wu[32];
  __shared__ float s_dobs[PP], s_dout[PP], s_logits[PP], s_pnew[PP];
  __shared__ int   s_idx[PP];

  int bx = blockIdx.x;
  int bn = bx & 7;           // col block 0..7
  int bm = bx >> 3;          // row block 0..15
  int tid = threadIdx.x;
  int tx = tid & 15, ty = tid >> 4;
  int lr = tid >> 2;
  int lk = (tid & 3) << 2;
  int w = tid >> 5, l = tid & 31;

  if (tid < 32) {
    s_wo[tid] = Wobs[EE + bn * 32 + tid];
    s_wu[tid] = Wout[bn * 32 + tid];
  }
  float bobs0 = bobs[0], bout0 = bout[0];

  const float* Br0 = g_Whh + (size_t)(bn * 128 + lr) * HH + lk;
  const float* Br1 = g_Whh + (size_t)(bn * 128 + lr + 64) * HH + lk;

  for (int t = 0; t < SS; t++) {
    int cur = t & 1, nxt = cur ^ 1;

    // load permutation (cross-CTA data -> L2) and xg slice (read-only, pre-kernel)
    if (tid < 128) s_perm[tid] = __ldcg(&g_perm[bm * 128 + tid]);
    {
      const float* src = g_xg + (size_t)(t * BB) * G4 + bn * 128;
      for (int e = tid; e < BB * 128; e += 256) {
        int b = e >> 7, col = e & 127;
        s_xgb[b][col] = src[(size_t)b * G4 + col];
      }
    }
    __syncthreads();

    const float* __restrict__ Acur = g_hbuf[cur];
    const float* Ar0 = Acur + (size_t)s_perm[lr] * HH + lk;
    const float* Ar1 = Acur + (size_t)s_perm[lr + 64] * HH + lk;

    unsigned long long acc2[8][4];
#pragma unroll
    for (int i = 0; i < 8; i++)
#pragma unroll
      for (int j = 0; j < 4; j++) acc2[i][j] = 0ull;

    // A/C state is written by other CTAs within this launch -> bypass L1 (.cg)
    float4 pa0 = __ldcg((const float4*)(Ar0));
    float4 pa1 = __ldcg((const float4*)(Ar1));
    float4 pb0 = *(const float4*)(Br0);
    float4 pb1 = *(const float4*)(Br1);

    for (int k0 = 0; k0 < HH; k0 += 16) {
      As[lk + 0][lr] = pa0.x; As[lk + 1][lr] = pa0.y; As[lk + 2][lr] = pa0.z; As[lk + 3][lr] = pa0.w;
      As[lk + 0][lr + 64] = pa1.x; As[lk + 1][lr + 64] = pa1.y; As[lk + 2][lr + 64] = pa1.z; As[lk + 3][lr + 64] = pa1.w;
      Bs[lk + 0][lr] = pb0.x; Bs[lk + 1][lr] = pb0.y; Bs[lk + 2][lr] = pb0.z; Bs[lk + 3][lr] = pb0.w;
      Bs[lk + 0][lr + 64] = pb1.x; Bs[lk + 1][lr + 64] = pb1.y; Bs[lk + 2][lr + 64] = pb1.z; Bs[lk + 3][lr + 64] = pb1.w;
      __syncthreads();
      if (k0 + 16 < HH) {
        pa0 = __ldcg((const float4*)(Ar0 + k0 + 16));
        pa1 = __ldcg((const float4*)(Ar1 + k0 + 16));
        pb0 = *(const float4*)(Br0 + k0 + 16);
        pb1 = *(const float4*)(Br1 + k0 + 16);
      }
#pragma unroll
      for (int kk = 0; kk < 16; kk++) {
        float4 av0 = *(const float4*)&As[kk][ty * 8];
        float4 av1 = *(const float4*)&As[kk][ty * 8 + 4];
        ulonglong2 bq0 = *(const ulonglong2*)&Bs[kk][tx * 8];
        ulonglong2 bq1 = *(const ulonglong2*)&Bs[kk][tx * 8 + 4];
        float av[8] = {av0.x, av0.y, av0.z, av0.w, av1.x, av1.y, av1.z, av1.w};
#pragma unroll
        for (int i = 0; i < 8; i++) {
          unsigned long long a2 = dup2(av[i]);
          ffma2(acc2[i][0], a2, bq0.x);
          ffma2(acc2[i][1], a2, bq0.y);
          ffma2(acc2[i][2], a2, bq1.x);
          ffma2(acc2[i][3], a2, bq1.y);
        }
      }
      __syncthreads();
    }

    // epilogue: LSTM cell + partial dots
    {
      int ul0 = tx * 2;
      int u0 = bn * 32 + ul0;
      float* __restrict__ Hn = g_hbuf[nxt];
      float* __restrict__ Cn = g_cbuf[nxt];
      const float* __restrict__ Cc = g_cbuf[cur];
      float w_o0 = s_wo[ul0], w_o1 = s_wo[ul0 + 1];
      float w_u0 = s_wu[ul0], w_u1 = s_wu[ul0 + 1];

      float obsr[8], outr[8];
#pragma unroll
      for (int i = 0; i < 8; i++) {
        int lrow = ty * 8 + i;
        int row = bm * 128 + lrow;
        int b = lrow & 31;
        int src = s_perm[lrow];
        float4 xv0 = *(const float4*)&s_xgb[b][tx * 8];
        float4 xv1 = *(const float4*)&s_xgb[b][tx * 8 + 4];
        float2 cold = __ldcg((const float2*)(Cc + (size_t)src * HH + u0));
        float a0, a1, a2v, a3, a4, a5, a6, a7;
        unpk2(acc2[i][0], a0, a1);
        unpk2(acc2[i][1], a2v, a3);
        unpk2(acc2[i][2], a4, a5);
        unpk2(acc2[i][3], a6, a7);
        float ig0 = a0 + xv0.x, fg0 = a1 + xv0.y, gg0 = a2v + xv0.z, og0 = a3 + xv0.w;
        float c10 = sigm(fg0) * cold.x + sigm(ig0) * tanhf(gg0);
        float h10 = sigm(og0) * tanhf(c10);
        float ig1 = a4 + xv1.x, fg1 = a5 + xv1.y, gg1 = a6 + xv1.z, og1 = a7 + xv1.w;
        float c11 = sigm(fg1) * cold.y + sigm(ig1) * tanhf(gg1);
        float h11 = sigm(og1) * tanhf(c11);
        *(float2*)(Hn + (size_t)row * HH + u0) = make_float2(h10, h11);
        *(float2*)(Cn + (size_t)row * HH + u0) = make_float2(c10, c11);
        obsr[i] = w_o0 * h10 + w_o1 * h11;
        outr[i] = w_u0 * h10 + w_u1 * h11;
      }
#pragma unroll
      for (int off = 8; off; off >>= 1) {
#pragma unroll
        for (int i = 0; i < 8; i++) {
          obsr[i] += __shfl_xor_sync(0xffffffffu, obsr[i], off);
          outr[i] += __shfl_xor_sync(0xffffffffu, outr[i], off);
        }
      }
      if (tx == 0) {
#pragma unroll
        for (int i = 0; i < 8; i++) {
          int row = bm * 128 + ty * 8 + i;
          g_pobs[bn][row] = obsr[i];
          g_pout[bn][row] = outr[i];
        }
      }
    }

    grid_sync();   // partials + new h/c visible grid-wide

    // ------------- resample: CTAs 0..31, one per batch -------------
    if (bx < BB) {
      int b = bx;
      if (tid < PP) {
        int r = tid * BB + b;
        float so = 0.0f, du = 0.0f;
#pragma unroll
        for (int nb = 0; nb < 8; nb++) {
          so += __ldcg(&g_pobs[nb][r]);
          du += __ldcg(&g_pout[nb][r]);
        }
        s_dobs[tid] = so; s_dout[tid] = du;
      }
      __syncthreads();

      if (w == 0) {
        float xd = g_xdot[t * BB + b] + bobs0;
        float v0 = s_dobs[l] + xd + __ldcg(&g_p[l * BB + b]);
        float v1 = s_dobs[l + 32] + xd + __ldcg(&g_p[(l + 32) * BB + b]);
        float m = fmaxf(v0, v1);
#pragma unroll
        for (int off = 16; off; off >>= 1) m = fmaxf(m, __shfl_xor_sync(0xffffffffu, m, off));
        float es = expf(v0 - m) + expf(v1 - m);
#pragma unroll
        for (int off = 16; off; off >>= 1) es += __shfl_xor_sync(0xffffffffu, es, off);
        float ls = logf(es);
        float q0 = v0 - m - ls, q1 = v1 - m - ls;
        s_logits[l] = logf(__fadd_rn(__fmul_rn(ALPHA_F, expf(q0)), CMIX_F));
        s_logits[l + 32] = logf(__fadd_rn(__fmul_rn(ALPHA_F, expf(q1)), CMIX_F));
      }
      __syncthreads();

      uint2 sub = g_sub[t];
      for (int i = w; i < PP; i += 8) {
        uint32_t base = (uint32_t)(i * NL + b * PP);
        float g0 = gumbel_from(sub.x, sub.y, base + (uint32_t)l) + s_logits[l];
        float g1 = gumbel_from(sub.x, sub.y, base + (uint32_t)(l + 32)) + s_logits[l + 32];
        float best = g0; int bi = l;
        if (g1 > best) { best = g1; bi = l + 32; }
#pragma unroll
        for (int off = 16; off; off >>= 1) {
          float ov = __shfl_xor_sync(0xffffffffu, best, off);
          int oi = __shfl_xor_sync(0xffffffffu, bi, off);
          if (ov > best || (ov == best && oi < bi)) { best = ov; bi = oi; }
        }
        if (l == 0) s_idx[i] = bi;
      }
      __syncthreads();

      if (w == 0) {
        float lw0 = s_logits[s_idx[l]];
        float lw1 = s_logits[s_idx[l + 32]];
        float m2 = fmaxf(lw0, lw1);
#pragma unroll
        for (int off = 16; off; off >>= 1) m2 = fmaxf(m2, __shfl_xor_sync(0xffffffffu, m2, off));
        float es = expf(lw0 - m2) + expf(lw1 - m2);
#pragma unroll
        for (int off = 16; off; off >>= 1) es += __shfl_xor_sync(0xffffffffu, es, off);
        float ls2 = logf(es);
        float pn0 = lw0 - m2 - ls2, pn1 = lw1 - m2 - ls2;
        s_pnew[l] = pn0; s_pnew[l + 32] = pn1;
        float yl = expf(pn0) * s_dout[s_idx[l]] + expf(pn1) * s_dout[s_idx[l + 32]];
#pragma unroll
        for (int off = 16; off; off >>= 1) yl += __shfl_xor_sync(0xffffffffu, yl, off);
        if (l == 0) out[t * BB + b] = lrelu(yl + bout0);
      }
      __syncthreads();

      if (tid < PP) {
        int i = tid;
        float d = s_dout[s_idx[i]] + bout0;
        out[SS * BB + (size_t)t * NL + i * BB + b] = lrelu(d);
        g_p[i * BB + b] = s_pnew[i];
        g_perm[i * BB + b] = s_idx[i] * BB + b;
      }
    }

    grid_sync();   // perm + p visible before next step's GEMM
  }
}

// ---------------- launch ----------------
extern "C" void kernel_launch(void* const* d_in, const int* in_sizes, int n_in,
                              void* d_out, int out_size) {
  const float* obs  = (const float*)d_in[0];
  const float* h0   = (const float*)d_in[1];
  const float* c0   = (const float*)d_in[2];
  const float* Wih  = (const float*)d_in[3];
  const float* bih  = (const float*)d_in[4];
  const float* Whh  = (const float*)d_in[5];
  const float* bhh  = (const float*)d_in[6];
  const float* Wobs = (const float*)d_in[7];
  const float* bobs = (const float*)d_in[8];
  const float* Wout = (const float*)d_in[9];
  const float* bout = (const float*)d_in[10];
  float* out = (float*)d_out;

  k_prep_keys<<<1, 1>>>();
  k_init<<<(NL * HH + 255) / 256, 256>>>(h0, c0);
  k_permW<<<G4, HH>>>(Whh, Wih, bih, bhh);
  k_xg2<<<dim3(8, 32), 256>>>(obs);
  k_xdot<<<SS * BB / 8, 256>>>(obs, Wobs);
  k_main<<<NCTA, 256>>>(Wobs, bobs, Wout, bout, out);
  (void)in_sizes; (void)n_in; (void)out_size;
}

// round 8
// speedup vs baseline: 2.6071x; 1.1108x over previous
#include <cuda_runtime.h>
#include <cuda_fp16.h>
#include <cstdint>

#define PP 64
#define HH 256
#define EE 64
#define BB 32
#define SS 128
#define G4 1024
#define NL 2048
#define NCTA 128

#define ALPHA_F 0.1f
#define CMIX_F  0.0140625f
#define TINY_F  1.17549435e-38f

// ---------------- device scratch ----------------
__device__ float g_xg[SS * BB * G4];          // x@Wih^T + biases, gate-permuted cols
__device__ float g_xdot[SS * BB];
__device__ float g_Wih[G4 * EE];              // gate-permuted
__device__ float g_bias[G4];
__device__ __half g_W16[2][G4 * HH];          // Whh gate-permuted fp16 splits, row-major
__device__ __half g_h16[2][2][NL * HH];       // [pingpong][split] h fp16 splits, row-major
__device__ float g_c[2][NL * HH];             // ping-pong c
__device__ int   g_perm[NL];
__device__ float g_p[NL];
__device__ float g_pobs[8][NL];
__device__ float g_pout[8][NL];
__device__ uint2 g_sub[SS];
__device__ unsigned int g_barc, g_barg;

// ---------------- mma.sync helper (baseline PTX, works on compute_103) ----------------
__device__ __forceinline__ void mma16816(float* d, uint32_t a0, uint32_t a1,
                                         uint32_t a2, uint32_t a3,
                                         uint32_t b0, uint32_t b1) {
  asm volatile(
    "mma.sync.aligned.m16n8k16.row.col.f32.f16.f16.f32 "
    "{%0,%1,%2,%3}, {%4,%5,%6,%7}, {%8,%9}, {%0,%1,%2,%3};"
    : "+f"(d[0]), "+f"(d[1]), "+f"(d[2]), "+f"(d[3])
    : "r"(a0), "r"(a1), "r"(a2), "r"(a3), "r"(b0), "r"(b1));
}

// ---------------- grid barrier (128 CTAs, all resident) ----------------
__device__ __forceinline__ void grid_sync() {
  __syncthreads();
  if (threadIdx.x == 0) {
    __threadfence();
    unsigned int gen = *(volatile unsigned int*)&g_barg;
    if (atomicAdd(&g_barc, 1u) == NCTA - 1u) {
      atomicExch(&g_barc, 0u);
      __threadfence();
      atomicAdd(&g_barg, 1u);
    } else {
      while (*(volatile unsigned int*)&g_barg == gen) { __nanosleep(64); }
    }
    __threadfence();
  }
  __syncthreads();
}

// ---------------- threefry / gumbel ----------------
__device__ __forceinline__ void tf2x32(uint32_t k0, uint32_t k1, uint32_t x0, uint32_t x1,
                                       uint32_t& o0, uint32_t& o1) {
  uint32_t ks2 = k0 ^ k1 ^ 0x1BD11BDAu;
  x0 += k0; x1 += k1;
#define TFR(r) { x0 += x1; x1 = (x1 << (r)) | (x1 >> (32 - (r))); x1 ^= x0; }
  TFR(13) TFR(15) TFR(26) TFR(6)   x0 += k1;  x1 += ks2 + 1u;
  TFR(17) TFR(29) TFR(16) TFR(24)  x0 += ks2; x1 += k0  + 2u;
  TFR(13) TFR(15) TFR(26) TFR(6)   x0 += k0;  x1 += k1  + 3u;
  TFR(17) TFR(29) TFR(16) TFR(24)  x0 += k1;  x1 += ks2 + 4u;
  TFR(13) TFR(15) TFR(26) TFR(6)   x0 += ks2; x1 += k0  + 5u;
#undef TFR
  o0 = x0; o1 = x1;
}
__device__ __forceinline__ float gumbel_from(uint32_t k0, uint32_t k1, uint32_t flat) {
  uint32_t o0, o1;
  tf2x32(k0, k1, 0u, flat, o0, o1);
  uint32_t bits = o0 ^ o1;
  float f = __uint_as_float((bits >> 9) | 0x3F800000u) - 1.0f;
  f = fmaxf(f, TINY_F);
  return -logf(-logf(f));
}
__device__ __forceinline__ float sigm(float x) { return 1.0f / (1.0f + expf(-x)); }
__device__ __forceinline__ float lrelu(float x) { return x >= 0.0f ? x : 0.01f * x; }

// ---------------- prologue kernels ----------------
__global__ void k_prep_keys() {
  if (threadIdx.x == 0 && blockIdx.x == 0) {
    uint32_t k0 = 0u, k1 = 42u;
    for (int t = 0; t < SS; t++) {
      uint32_t n0, n1, s0, s1;
      tf2x32(k0, k1, 0u, 0u, n0, n1);
      tf2x32(k0, k1, 0u, 1u, s0, s1);
      g_sub[t] = make_uint2(s0, s1);
      k0 = n0; k1 = n1;
    }
  }
}

__global__ void k_init(const float* __restrict__ h0, const float* __restrict__ c0) {
  int i = blockIdx.x * blockDim.x + threadIdx.x;
  if (i < NL * HH) {
    g_c[0][i] = c0[i];
    float v = h0[i];
    __half a1 = __float2half_rn(v);
    __half a2 = __float2half_rn(v - __half2float(a1));
    g_h16[0][0][i] = a1; g_h16[0][1][i] = a2;
  }
  if (i < NL) { g_p[i] = -4.158883083359672f; g_perm[i] = i; }
}

// gate-permute rows (n = 4u+g <- g*H+u), split Whh to fp16x2, pack Wih + bias
__global__ void k_permW(const float* __restrict__ Whh, const float* __restrict__ Wih,
                        const float* __restrict__ bih, const float* __restrict__ bhh) {
  int n = blockIdx.x;
  int u = n >> 2, g = n & 3;
  int src = g * HH + u;
  int k = threadIdx.x;
  float v = Whh[src * HH + k];
  __half b1 = __float2half_rn(v);
  __half b2 = __float2half_rn(v - __half2float(b1));
  g_W16[0][n * HH + k] = b1;
  g_W16[1][n * HH + k] = b2;
  if (k < EE) g_Wih[n * EE + k] = Wih[src * EE + k];
  if (k == 0) g_bias[n] = bih[src] + bhh[src];
}

// xg = obs-rows @ g_Wih^T + g_bias  (4096x1024, K=64)
__global__ void __launch_bounds__(256, 1) k_xg2(const float* __restrict__ obs) {
  __shared__ float As[EE][132];
  __shared__ float Bs[EE][132];
  int bn = blockIdx.x, bm = blockIdx.y, tid = threadIdx.x;
  for (int e = tid; e < 128 * 16; e += 256) {
    int row = e >> 4, c4 = (e & 15) * 4;
    int gr = bm * 128 + row;
    int t = gr >> 5, b = gr & 31;
    float4 v = *(const float4*)(obs + ((size_t)b * SS + t) * EE + c4);
    As[c4][row] = v.x; As[c4 + 1][row] = v.y; As[c4 + 2][row] = v.z; As[c4 + 3][row] = v.w;
  }
  for (int e = tid; e < 128 * 16; e += 256) {
    int row = e >> 4, c4 = (e & 15) * 4;
    float4 v = *(const float4*)(g_Wih + (size_t)(bn * 128 + row) * EE + c4);
    Bs[c4][row] = v.x; Bs[c4 + 1][row] = v.y; Bs[c4 + 2][row] = v.z; Bs[c4 + 3][row] = v.w;
  }
  __syncthreads();
  int tx = tid & 15, ty = tid >> 4;
  float acc[8][8];
#pragma unroll
  for (int i = 0; i < 8; i++)
#pragma unroll
    for (int j = 0; j < 8; j++) acc[i][j] = 0.0f;
#pragma unroll 8
  for (int kk = 0; kk < EE; kk++) {
    float4 av0 = *(const float4*)&As[kk][ty * 8];
    float4 av1 = *(const float4*)&As[kk][ty * 8 + 4];
    float4 bv0 = *(const float4*)&Bs[kk][tx * 8];
    float4 bv1 = *(const float4*)&Bs[kk][tx * 8 + 4];
    float av[8] = {av0.x, av0.y, av0.z, av0.w, av1.x, av1.y, av1.z, av1.w};
    float bv[8] = {bv0.x, bv0.y, bv0.z, bv0.w, bv1.x, bv1.y, bv1.z, bv1.w};
#pragma unroll
    for (int i = 0; i < 8; i++)
#pragma unroll
      for (int j = 0; j < 8; j++) acc[i][j] = fmaf(av[i], bv[j], acc[i][j]);
  }
  float4 bi0 = *(const float4*)(g_bias + bn * 128 + tx * 8);
  float4 bi1 = *(const float4*)(g_bias + bn * 128 + tx * 8 + 4);
#pragma unroll
  for (int i = 0; i < 8; i++) {
    int gr = bm * 128 + ty * 8 + i;
    *(float4*)(g_xg + (size_t)gr * G4 + bn * 128 + tx * 8) =
        make_float4(acc[i][0] + bi0.x, acc[i][1] + bi0.y, acc[i][2] + bi0.z, acc[i][3] + bi0.w);
    *(float4*)(g_xg + (size_t)gr * G4 + bn * 128 + tx * 8 + 4) =
        make_float4(acc[i][4] + bi1.x, acc[i][5] + bi1.y, acc[i][6] + bi1.z, acc[i][7] + bi1.w);
  }
}

__global__ void k_xdot(const float* __restrict__ obs, const float* __restrict__ Wobs) {
  int r = blockIdx.x * 8 + (threadIdx.x >> 5);
  int l = threadIdx.x & 31;
  int t = r >> 5, b = r & 31;
  const float* x = obs + ((size_t)b * SS + t) * EE;
  float acc = fmaf(x[l], Wobs[l], x[l + 32] * Wobs[l + 32]);
#pragma unroll
  for (int off = 16; off; off >>= 1) acc += __shfl_xor_sync(0xffffffffu, acc, off);
  if (l == 0) g_xdot[r] = acc;
}

// ---------------- persistent main: mma.sync fp16x2 GEMM + cell + resample ----------------
// SMEM layout (dynamic): Bsm [2][128][264] halves (135168 B), Asm [2][128][72] (36864 B)
#define BSM_STRIDE 264
#define BSM_SPLIT  33792     // 128*264
#define ASM_STRIDE 72
#define ASM_SPLIT  9216      // 128*72
#define DYN_BYTES  (2*BSM_SPLIT*2 + 2*ASM_SPLIT*2)   // 172032

extern __shared__ __half dsm16[];

__global__ void __launch_bounds__(256, 1) k_main(
    const float* __restrict__ Wobs, const float* __restrict__ bobs,
    const float* __restrict__ Wout, const float* __restrict__ bout,
    float* __restrict__ out) {
  __shared__ float s_xgb[BB][132];
  __shared__ int   s_perm[128];
  __shared__ float s_wo[32], s_wu[32];
  __shared__ float s_dobs[PP], s_dout[PP], s_logits[PP], s_pnew[PP];
  __shared__ int   s_idx[PP];

  int bx = blockIdx.x, bn = bx & 7, bm = bx >> 3;
  int tid = threadIdx.x, w = tid >> 5, l = tid & 31;

  __half* Bsm = dsm16;
  __half* Asm = dsm16 + 2 * BSM_SPLIT;

  // one-time: B (Whh splits) -> smem, padded rows (conflict-free frags)
  {
    int s = tid >> 7, n = tid & 127;
    const uint4* src = (const uint4*)(g_W16[s] + (size_t)(bn * 128 + n) * HH);
    uint4* dst = (uint4*)(Bsm + s * BSM_SPLIT + n * BSM_STRIDE);
#pragma unroll
    for (int q = 0; q < 32; q++) dst[q] = src[q];
  }
  if (tid < 32) { s_wo[tid] = Wobs[EE + bn * 32 + tid]; s_wu[tid] = Wout[bn * 32 + tid]; }
  float bobs0 = bobs[0], bout0 = bout[0];

  int gr = (w << 4) + (l >> 2);      // A-frag row (w*16 + l/4)
  int qk = (l & 3) << 1;             // k offset within 16

  for (int t = 0; t < SS; t++) {
    int cur = t & 1, nxt = cur ^ 1;

    if (tid < 128) s_perm[tid] = __ldcg(&g_perm[bm * 128 + tid]);
    {
      const float* srcx = g_xg + (size_t)(t * BB) * G4 + bn * 128;
      for (int e = tid; e < BB * 128; e += 256) {
        int b2 = e >> 7, col = e & 127;
        s_xgb[b2][col] = srcx[(size_t)b2 * G4 + col];
      }
    }
    __syncthreads();

    float acc[16][4];
#pragma unroll
    for (int i = 0; i < 16; i++)
#pragma unroll
      for (int j = 0; j < 4; j++) acc[i][j] = 0.0f;

    for (int kc = 0; kc < 4; kc++) {
      // gather A chunk: thread -> (row = tid/2, split = tid&1), 64 halves = 8 uint4
      {
        int r = tid >> 1, s = tid & 1;
        int srow = s_perm[r];
        const uint4* src = (const uint4*)(g_h16[cur][s] + (size_t)srow * HH + kc * 64);
        uint4* dst = (uint4*)(Asm + s * ASM_SPLIT + r * ASM_STRIDE);
#pragma unroll
        for (int q = 0; q < 8; q++) dst[q] = __ldcg(src + q);
      }
      __syncthreads();
#pragma unroll
      for (int ps = 0; ps < 4; ps++) {
        const __half* Ab = Asm + (ps >> 1) * ASM_SPLIT;
        const __half* Bb = Bsm + (ps & 1) * BSM_SPLIT + kc * 64;
#pragma unroll
        for (int kk = 0; kk < 4; kk++) {
          int kl = (kk << 4) + qk;
          uint32_t a0 = *(const uint32_t*)(Ab + gr * ASM_STRIDE + kl);
          uint32_t a1 = *(const uint32_t*)(Ab + (gr + 8) * ASM_STRIDE + kl);
          uint32_t a2 = *(const uint32_t*)(Ab + gr * ASM_STRIDE + kl + 8);
          uint32_t a3 = *(const uint32_t*)(Ab + (gr + 8) * ASM_STRIDE + kl + 8);
          int kg = (kc << 6) + kl;   // wait: Bb already offset by kc*64; use kl here
#pragma unroll
          for (int nt = 0; nt < 16; nt++) {
            int n = (nt << 3) + (l >> 2);
            uint32_t b0 = *(const uint32_t*)(Bb + n * BSM_STRIDE + kl);
            uint32_t b1 = *(const uint32_t*)(Bb + n * BSM_STRIDE + kl + 8);
            mma16816(acc[nt], a0, a1, a2, a3, b0, b1);
          }
          (void)kg;
        }
      }
      __syncthreads();
    }

    // ---- epilogue: assemble gate quads via lane-pair shuffle, LSTM cell ----
    {
      int par = l & 1;                 // 0: rows gr, 1: rows gr+8
      int myhalf = (l >> 1) & 1;       // unit parity within ntile
      int rowloc = (w << 4) + (l >> 2) + (par ? 8 : 0);
      int grow = bm * 128 + rowloc;
      int b = rowloc & 31;
      int srow = s_perm[rowloc];
      const float* cold = g_c[cur] + (size_t)srow * HH + bn * 32;
      float* cnew = g_c[nxt] + (size_t)grow * HH + bn * 32;
      __half* h1p = g_h16[nxt][0] + (size_t)grow * HH + bn * 32;
      __half* h2p = g_h16[nxt][1] + (size_t)grow * HH + bn * 32;
      float pobs = 0.f, pout = 0.f;
#pragma unroll
      for (int nt = 0; nt < 16; nt++) {
        float e0 = __shfl_xor_sync(0xffffffffu, acc[nt][0], 1);
        float e1 = __shfl_xor_sync(0xffffffffu, acc[nt][1], 1);
        float e2 = __shfl_xor_sync(0xffffffffu, acc[nt][2], 1);
        float e3 = __shfl_xor_sync(0xffffffffu, acc[nt][3], 1);
        float ig, fg, gg, og;
        if (!par) { ig = acc[nt][0]; fg = acc[nt][1]; gg = e0; og = e1; }
        else      { ig = e2; fg = e3; gg = acc[nt][2]; og = acc[nt][3]; }
        int u = (nt << 1) + myhalf;
        float4 xv = *(const float4*)&s_xgb[b][u << 2];
        ig += xv.x; fg += xv.y; gg += xv.z; og += xv.w;
        float c1 = sigm(fg) * __ldcg(&cold[u]) + sigm(ig) * tanhf(gg);
        float h1 = sigm(og) * tanhf(c1);
        cnew[u] = c1;
        __half x1 = __float2half_rn(h1);
        __half x2 = __float2half_rn(h1 - __half2float(x1));
        h1p[u] = x1; h2p[u] = x2;
        pobs = fmaf(s_wo[u], h1, pobs);
        pout = fmaf(s_wu[u], h1, pout);
      }
      pobs += __shfl_xor_sync(0xffffffffu, pobs, 2);
      pout += __shfl_xor_sync(0xffffffffu, pout, 2);
      if ((l & 2) == 0) {
        g_pobs[bn][grow] = pobs;
        g_pout[bn][grow] = pout;
      }
    }

    grid_sync();

    // ---- resample: CTAs 0..31, one per batch ----
    if (bx < BB) {
      int b = bx;
      if (tid < PP) {
        int r = tid * BB + b;
        float so = 0.0f, du = 0.0f;
#pragma unroll
        for (int nb = 0; nb < 8; nb++) { so += __ldcg(&g_pobs[nb][r]); du += __ldcg(&g_pout[nb][r]); }
        s_dobs[tid] = so; s_dout[tid] = du;
      }
      __syncthreads();

      if (w == 0) {
        float xd = g_xdot[t * BB + b] + bobs0;
        float v0 = s_dobs[l] + xd + __ldcg(&g_p[l * BB + b]);
        float v1 = s_dobs[l + 32] + xd + __ldcg(&g_p[(l + 32) * BB + b]);
        float m = fmaxf(v0, v1);
#pragma unroll
        for (int off = 16; off; off >>= 1) m = fmaxf(m, __shfl_xor_sync(0xffffffffu, m, off));
        float es = expf(v0 - m) + expf(v1 - m);
#pragma unroll
        for (int off = 16; off; off >>= 1) es += __shfl_xor_sync(0xffffffffu, es, off);
        float ls = logf(es);
        float q0 = v0 - m - ls, q1 = v1 - m - ls;
        s_logits[l] = logf(__fadd_rn(__fmul_rn(ALPHA_F, expf(q0)), CMIX_F));
        s_logits[l + 32] = logf(__fadd_rn(__fmul_rn(ALPHA_F, expf(q1)), CMIX_F));
      }
      __syncthreads();

      uint2 sub = g_sub[t];
      for (int i = w; i < PP; i += 8) {
        uint32_t base = (uint32_t)(i * NL + b * PP);
        float g0 = gumbel_from(sub.x, sub.y, base + (uint32_t)l) + s_logits[l];
        float g1 = gumbel_from(sub.x, sub.y, base + (uint32_t)(l + 32)) + s_logits[l + 32];
        float best = g0; int bi = l;
        if (g1 > best) { best = g1; bi = l + 32; }
#pragma unroll
        for (int off = 16; off; off >>= 1) {
          float ov = __shfl_xor_sync(0xffffffffu, best, off);
          int oi = __shfl_xor_sync(0xffffffffu, bi, off);
          if (ov > best || (ov == best && oi < bi)) { best = ov; bi = oi; }
        }
        if (l == 0) s_idx[i] = bi;
      }
      __syncthreads();

      if (w == 0) {
        float lw0 = s_logits[s_idx[l]];
        float lw1 = s_logits[s_idx[l + 32]];
        float m2 = fmaxf(lw0, lw1);
#pragma unroll
        for (int off = 16; off; off >>= 1) m2 = fmaxf(m2, __shfl_xor_sync(0xffffffffu, m2, off));
        float es = expf(lw0 - m2) + expf(lw1 - m2);
#pragma unroll
        for (int off = 16; off; off >>= 1) es += __shfl_xor_sync(0xffffffffu, es, off);
        float ls2 = logf(es);
        float pn0 = lw0 - m2 - ls2, pn1 = lw1 - m2 - ls2;
        s_pnew[l] = pn0; s_pnew[l + 32] = pn1;
        float yl = expf(pn0) * s_dout[s_idx[l]] + expf(pn1) * s_dout[s_idx[l + 32]];
#pragma unroll
        for (int off = 16; off; off >>= 1) yl += __shfl_xor_sync(0xffffffffu, yl, off);
        if (l == 0) out[t * BB + b] = lrelu(yl + bout0);
      }
      __syncthreads();

      if (tid < PP) {
        int i = tid;
        float d = s_dout[s_idx[i]] + bout0;
        out[SS * BB + (size_t)t * NL + i * BB + b] = lrelu(d);
        g_p[i * BB + b] = s_pnew[i];
        g_perm[i * BB + b] = s_idx[i] * BB + b;
      }
    }

    grid_sync();
  }
}

// ---------------- launch ----------------
extern "C" void kernel_launch(void* const* d_in, const int* in_sizes, int n_in,
                              void* d_out, int out_size) {
  const float* obs  = (const float*)d_in[0];
  const float* h0   = (const float*)d_in[1];
  const float* c0   = (const float*)d_in[2];
  const float* Wih  = (const float*)d_in[3];
  const float* bih  = (const float*)d_in[4];
  const float* Whh  = (const float*)d_in[5];
  const float* bhh  = (const float*)d_in[6];
  const float* Wobs = (const float*)d_in[7];
  const float* bobs = (const float*)d_in[8];
  const float* Wout = (const float*)d_in[9];
  const float* bout = (const float*)d_in[10];
  float* out = (float*)d_out;

  cudaFuncSetAttribute(k_main, cudaFuncAttributeMaxDynamicSharedMemorySize, DYN_BYTES);

  k_prep_keys<<<1, 1>>>();
  k_init<<<(NL * HH + 255) / 256, 256>>>(h0, c0);
  k_permW<<<G4, HH>>>(Whh, Wih, bih, bhh);
  k_xg2<<<dim3(8, 32), 256>>>(obs);
  k_xdot<<<SS * BB / 8, 256>>>(obs, Wobs);
  k_main<<<NCTA, 256, DYN_BYTES>>>(Wobs, bobs, Wout, bout, out);
  (void)in_sizes; (void)n_in; (void)out_size;
}